// round 1
// baseline (speedup 1.0000x reference)
#include <cuda_runtime.h>
#include <math.h>

#define BATCH 32
#define TLEN  600
#define CH    64
#define NSEG  50
#define NH    512
#define NPAIR (CH*(CH-1)/2)      // 2016
#define LOGSIG_CH (CH + NPAIR)   // 2080
#define INSZ  (LOGSIG_CH + CH)   // 2144
#define G4    (4*NH)             // 2048
#define MROWS (BATCH*NSEG)       // 1600

// ---- scratch (no allocations allowed) ----
__device__ float g_feats[MROWS * INSZ];     // 13.7 MB
__device__ float g_gx[MROWS * G4];          // 13.1 MB
__device__ float g_hbuf[2][BATCH * NH];
__device__ float g_cbuf[BATCH * NH];

struct SegArgs { int start[NSEG]; int len[NSEG]; };

// ============================================================
// Kernel 1: per-(batch,segment) depth-2 log-signature features
//   feats[bs] = [ inc(64) | A_triu(2016) | x_start(64) ]
// A[i][j] = 0.5*( sum_t (x_i[t]*x_j[t+1] - x_j[t]*x_i[t+1])
//                 - xa_i*inc_j + xa_j*inc_i )
// ============================================================
__global__ void k_feats(const float* __restrict__ x, SegArgs seg) {
    int bs = blockIdx.x;
    int b = bs / NSEG, s = bs % NSEG;
    int st = seg.start[s], len = seg.len[s];   // len <= 16

    __shared__ float xs[17][CH];
    const float* xp = x + ((size_t)b * TLEN + st) * CH;
    for (int idx = threadIdx.x; idx < (len + 1) * CH; idx += blockDim.x)
        xs[idx >> 6][idx & 63] = xp[idx];
    __syncthreads();

    float* fr = g_feats + (size_t)bs * INSZ;

    if (threadIdx.x < CH) {
        int c = threadIdx.x;
        float xa = xs[0][c], xe = xs[len][c];
        fr[c] = xe - xa;             // inc
        fr[LOGSIG_CH + c] = xa;      // start point
    }

    for (int p = threadIdx.x; p < NPAIR; p += blockDim.x) {
        // linear index -> (i,j), i<j, row-major upper triangle
        int i = 0, rem = p;
        while (rem >= (CH - 1 - i)) { rem -= (CH - 1 - i); i++; }
        int j = i + 1 + rem;

        float acc = 0.0f;
        for (int t = 0; t < len; t++)
            acc += xs[t][i] * xs[t + 1][j] - xs[t][j] * xs[t + 1][i];

        float xai = xs[0][i], xaj = xs[0][j];
        float inci = xs[len][i] - xai;
        float incj = xs[len][j] - xaj;
        fr[CH + p] = 0.5f * (acc - xai * incj + xaj * inci);
    }
}

// ============================================================
// Kernel 2: gx = feats @ w_ih^T + (b_ih + b_hh)
//   M=1600, N=2048, K=2144. Both operands K-major (NT GEMM).
//   64x64 block tile, BK=16, 256 threads, 4x4 microtile.
// ============================================================
#define BM 64
#define BN 64
#define BK 16

__global__ void k_gemm_gx(const float* __restrict__ w_ih,
                          const float* __restrict__ b_ih,
                          const float* __restrict__ b_hh) {
    __shared__ __align__(16) float As[BK][BM];
    __shared__ __align__(16) float Bs[BK][BN];

    int tx = threadIdx.x;            // 0..255
    int m0 = blockIdx.y * BM;
    int n0 = blockIdx.x * BN;

    int lr = tx >> 2;                // 0..63 tile row
    int lk = (tx & 3) * 4;           // 0,4,8,12

    const float* Ap = g_feats + (size_t)(m0 + lr) * INSZ + lk;
    const float* Bp = w_ih    + (size_t)(n0 + lr) * INSZ + lk;

    int tm = (tx & 15) * 4;
    int tn = (tx >> 4) * 4;

    float acc[4][4] = {};

    for (int k0 = 0; k0 < INSZ; k0 += BK) {
        float4 av = *(const float4*)(Ap + k0);
        float4 bv = *(const float4*)(Bp + k0);
        As[lk + 0][lr] = av.x; As[lk + 1][lr] = av.y;
        As[lk + 2][lr] = av.z; As[lk + 3][lr] = av.w;
        Bs[lk + 0][lr] = bv.x; Bs[lk + 1][lr] = bv.y;
        Bs[lk + 2][lr] = bv.z; Bs[lk + 3][lr] = bv.w;
        __syncthreads();

        #pragma unroll
        for (int kk = 0; kk < BK; kk++) {
            float4 a4 = *(const float4*)&As[kk][tm];
            float4 b4 = *(const float4*)&Bs[kk][tn];
            float a[4] = {a4.x, a4.y, a4.z, a4.w};
            float bb[4] = {b4.x, b4.y, b4.z, b4.w};
            #pragma unroll
            for (int i = 0; i < 4; i++)
                #pragma unroll
                for (int j = 0; j < 4; j++)
                    acc[i][j] = fmaf(a[i], bb[j], acc[i][j]);
        }
        __syncthreads();
    }

    #pragma unroll
    for (int i = 0; i < 4; i++) {
        int m = m0 + tm + i;
        #pragma unroll
        for (int j = 0; j < 4; j++) {
            int n = n0 + tn + j;
            g_gx[(size_t)m * G4 + n] = acc[i][j] + b_ih[n] + b_hh[n];
        }
    }
}

// ============================================================
// Kernel 3: one LSTM step.
//   grid = 128 blocks (4 hidden units each), 128 threads (32 b x 4 u).
//   Each thread computes all 4 gate dots (K=512) for its (b, n),
//   then the cell update. h double-buffered across steps.
// ============================================================
__global__ void k_lstm_step(const float* __restrict__ whh,
                            float* __restrict__ out, int s) {
    int tid = threadIdx.x;
    int b = tid & 31;
    int u = tid >> 5;                     // 0..3
    int n = blockIdx.x * 4 + u;

    const float* hin = g_hbuf[(s + 1) & 1];
    float*       hout = g_hbuf[s & 1];

    float acc0 = 0.f, acc1 = 0.f, acc2 = 0.f, acc3 = 0.f;

    if (s > 0) {
        __shared__ float hs[128][33];
        const float* w0 = whh + (size_t)(0 * NH + n) * NH;
        const float* w1 = whh + (size_t)(1 * NH + n) * NH;
        const float* w2 = whh + (size_t)(2 * NH + n) * NH;
        const float* w3 = whh + (size_t)(3 * NH + n) * NH;

        for (int k0 = 0; k0 < NH; k0 += 128) {
            for (int idx = tid; idx < 128 * 32; idx += 128) {
                int bb = idx >> 7, kk = idx & 127;
                hs[kk][bb] = hin[bb * NH + k0 + kk];
            }
            __syncthreads();
            #pragma unroll 8
            for (int kk = 0; kk < 128; kk++) {
                float hv = hs[kk][b];
                acc0 = fmaf(hv, w0[k0 + kk], acc0);
                acc1 = fmaf(hv, w1[k0 + kk], acc1);
                acc2 = fmaf(hv, w2[k0 + kk], acc2);
                acc3 = fmaf(hv, w3[k0 + kk], acc3);
            }
            __syncthreads();
        }
    }

    const float* gxr = g_gx + ((size_t)b * NSEG + s) * G4;
    float gi = gxr[n]          + acc0;
    float gf = gxr[NH + n]     + acc1;
    float gg = gxr[2 * NH + n] + acc2;
    float go = gxr[3 * NH + n] + acc3;

    gi = 1.0f / (1.0f + expf(-gi));
    gf = 1.0f / (1.0f + expf(-gf));
    gg = tanhf(gg);
    go = 1.0f / (1.0f + expf(-go));

    float cprev = (s == 0) ? 0.0f : g_cbuf[b * NH + n];
    float cn = gf * cprev + gi * gg;
    float hn = go * tanhf(cn);

    g_cbuf[b * NH + n] = cn;
    hout[b * NH + n] = hn;
    out[((size_t)b * NSEG + s) * NH + n] = hn;
}

// ============================================================
extern "C" void kernel_launch(void* const* d_in, const int* in_sizes, int n_in,
                              void* d_out, int out_size) {
    const float* x    = (const float*)d_in[0];
    const float* w_ih = (const float*)d_in[1];
    const float* w_hh = (const float*)d_in[2];
    const float* b_ih = (const float*)d_in[3];
    const float* b_hh = (const float*)d_in[4];
    float* out = (float*)d_out;

    // Replicate np.linspace(1,600,51) + round-half-even exactly.
    SegArgs seg;
    const double step = 599.0 / 50.0;
    int tv[NSEG + 1];
    for (int i = 0; i <= NSEG; i++)
        tv[i] = (int)nearbyint(1.0 + step * (double)i);
    tv[NSEG] = TLEN;  // linspace forces the endpoint
    for (int s = 0; s < NSEG; s++) {
        seg.start[s] = tv[s] - 1;
        int len = tv[s + 1] - tv[s];
        if (len > 16) len = 16;   // safety clamp (actual lens are 11-12)
        seg.len[s] = len;
    }

    k_feats<<<MROWS, 256>>>(x, seg);

    dim3 g2(G4 / BN, MROWS / BM);  // 32 x 25
    k_gemm_gx<<<g2, 256>>>(w_ih, b_ih, b_hh);

    for (int s = 0; s < NSEG; s++)
        k_lstm_step<<<NH / 4, 128>>>(w_hh, out, s);
}

// round 3
// speedup vs baseline: 2.7967x; 2.7967x over previous
#include <cuda_runtime.h>
#include <math.h>

#define BATCH 32
#define TLEN  600
#define CH    64
#define NSEG  50
#define NH    512
#define NPAIR (CH*(CH-1)/2)      // 2016
#define LOGSIG_CH (CH + NPAIR)   // 2080
#define INSZ  (LOGSIG_CH + CH)   // 2144
#define G4    (4*NH)             // 2048
#define MROWS (BATCH*NSEG)       // 1600

#define NBLK  128                // persistent LSTM blocks (<=148, all resident)
#define NU    4                  // hidden units per block (NBLK*NU = NH)
#define HS    516                // padded h row stride (conflict-free float4 LDS)

// ---- scratch (no allocations allowed) ----
__device__ float g_feats[MROWS * INSZ];     // 13.7 MB
__device__ float g_gx[MROWS * G4];          // 13.1 MB
__device__ float g_hbuf[2][BATCH * NH];
__device__ unsigned int g_bar[NSEG];

struct SegArgs { int start[NSEG]; int len[NSEG]; };

// ============================================================
// Kernel 0: reset grid-barrier counters (graph replays reuse them)
// ============================================================
__global__ void k_reset() {
    int i = threadIdx.x;
    if (i < NSEG) g_bar[i] = 0u;
}

// ============================================================
// Kernel 1: per-(batch,segment) depth-2 log-signature features
// ============================================================
__global__ void k_feats(const float* __restrict__ x, SegArgs seg) {
    int bs = blockIdx.x;
    int b = bs / NSEG, s = bs % NSEG;
    int st = seg.start[s], len = seg.len[s];   // len <= 16

    __shared__ float xs[17][CH];
    const float* xp = x + ((size_t)b * TLEN + st) * CH;
    for (int idx = threadIdx.x; idx < (len + 1) * CH; idx += blockDim.x)
        xs[idx >> 6][idx & 63] = xp[idx];
    __syncthreads();

    float* fr = g_feats + (size_t)bs * INSZ;

    if (threadIdx.x < CH) {
        int c = threadIdx.x;
        float xa = xs[0][c], xe = xs[len][c];
        fr[c] = xe - xa;             // inc
        fr[LOGSIG_CH + c] = xa;      // start point
    }

    for (int p = threadIdx.x; p < NPAIR; p += blockDim.x) {
        int i = 0, rem = p;
        while (rem >= (CH - 1 - i)) { rem -= (CH - 1 - i); i++; }
        int j = i + 1 + rem;

        float acc = 0.0f;
        for (int t = 0; t < len; t++)
            acc += xs[t][i] * xs[t + 1][j] - xs[t][j] * xs[t + 1][i];

        float xai = xs[0][i], xaj = xs[0][j];
        float inci = xs[len][i] - xai;
        float incj = xs[len][j] - xaj;
        fr[CH + p] = 0.5f * (acc - xai * incj + xaj * inci);
    }
}

// ============================================================
// Kernel 2: gx = feats @ w_ih^T + (b_ih + b_hh)
//   M=1600, N=2048, K=2144 (NT). 64x64 tile, BK=16, 256 thr, 4x4.
// ============================================================
#define BM 64
#define BN 64
#define BK 16

__global__ void k_gemm_gx(const float* __restrict__ w_ih,
                          const float* __restrict__ b_ih,
                          const float* __restrict__ b_hh) {
    __shared__ __align__(16) float As[BK][BM];
    __shared__ __align__(16) float Bs[BK][BN];

    int tx = threadIdx.x;
    int m0 = blockIdx.y * BM;
    int n0 = blockIdx.x * BN;

    int lr = tx >> 2;
    int lk = (tx & 3) * 4;

    const float* Ap = g_feats + (size_t)(m0 + lr) * INSZ + lk;
    const float* Bp = w_ih    + (size_t)(n0 + lr) * INSZ + lk;

    int tm = (tx & 15) * 4;
    int tn = (tx >> 4) * 4;

    float acc[4][4] = {};

    for (int k0 = 0; k0 < INSZ; k0 += BK) {
        float4 av = *(const float4*)(Ap + k0);
        float4 bv = *(const float4*)(Bp + k0);
        As[lk + 0][lr] = av.x; As[lk + 1][lr] = av.y;
        As[lk + 2][lr] = av.z; As[lk + 3][lr] = av.w;
        Bs[lk + 0][lr] = bv.x; Bs[lk + 1][lr] = bv.y;
        Bs[lk + 2][lr] = bv.z; Bs[lk + 3][lr] = bv.w;
        __syncthreads();

        #pragma unroll
        for (int kk = 0; kk < BK; kk++) {
            float4 a4 = *(const float4*)&As[kk][tm];
            float4 b4 = *(const float4*)&Bs[kk][tn];
            float a[4] = {a4.x, a4.y, a4.z, a4.w};
            float bb[4] = {b4.x, b4.y, b4.z, b4.w};
            #pragma unroll
            for (int i = 0; i < 4; i++)
                #pragma unroll
                for (int j = 0; j < 4; j++)
                    acc[i][j] = fmaf(a[i], bb[j], acc[i][j]);
        }
        __syncthreads();
    }

    #pragma unroll
    for (int i = 0; i < 4; i++) {
        int m = m0 + tm + i;
        #pragma unroll
        for (int j = 0; j < 4; j++) {
            int n = n0 + tn + j;
            g_gx[(size_t)m * G4 + n] = acc[i][j] + b_ih[n] + b_hh[n];
        }
    }
}

// ============================================================
// Kernel 3: PERSISTENT LSTM. One launch runs all 50 steps.
//   128 blocks x 128 threads, all resident. Block owns 4 hidden
//   units; its 16 w_hh gate rows (32 KB) live in SMEM for the
//   whole kernel. c stays in registers. h double-buffered in
//   global, synchronized by a per-step grid spin barrier.
//   NOTE: g_gx is referenced directly (device symbol) — passing
//   it as a host-side kernel arg is invalid.
// ============================================================
__global__ void k_lstm_persist(const float* __restrict__ whh,
                               float* __restrict__ out) {
    extern __shared__ float smem[];
    float* ws = smem;                    // [4 gates][NU][NH] = 16*512
    float* hs = smem + 4 * NU * NH;      // [BATCH][HS] padded

    int tid = threadIdx.x;
    int b = tid & 31;
    int u = tid >> 5;
    int n0 = blockIdx.x * NU;
    int n = n0 + u;

    // Load this block's w_hh slice once: row (g*NH + n0+uu), g=0..3, uu=0..3
    for (int i = tid; i < 4 * NU * (NH / 4); i += NBLK) {
        int row = i / (NH / 4);          // 0..15  (g*NU + uu)
        int kq  = i % (NH / 4);
        int g = row >> 2, uu = row & 3;
        *(float4*)&ws[row * NH + 4 * kq] =
            *(const float4*)&whh[((size_t)g * NH + n0 + uu) * NH + 4 * kq];
    }
    __syncthreads();

    const float* wi = ws + (0 * NU + u) * NH;
    const float* wf = ws + (1 * NU + u) * NH;
    const float* wg = ws + (2 * NU + u) * NH;
    const float* wo = ws + (3 * NU + u) * NH;
    float* hrow = hs + b * HS;

    float cc = 0.0f;

    for (int s = 0; s < NSEG; s++) {
        float acc0 = 0.f, acc1 = 0.f, acc2 = 0.f, acc3 = 0.f;

        if (s > 0) {
            // stage h(s-1) into SMEM (L2-coherent loads; skip L1)
            const float4* src = (const float4*)g_hbuf[(s + 1) & 1];
            for (int i = tid; i < BATCH * (NH / 4); i += NBLK) {
                int bb = i >> 7;         // /128
                int kq = i & 127;
                float4 v = __ldcg(src + i);
                *(float4*)&hs[bb * HS + 4 * kq] = v;
            }
            __syncthreads();

            #pragma unroll 4
            for (int kq = 0; kq < NH / 4; kq++) {
                float4 hv = *(const float4*)(hrow + 4 * kq);
                float4 a = *(const float4*)(wi + 4 * kq);
                float4 f = *(const float4*)(wf + 4 * kq);
                float4 g = *(const float4*)(wg + 4 * kq);
                float4 o = *(const float4*)(wo + 4 * kq);
                acc0 = fmaf(hv.x, a.x, acc0); acc0 = fmaf(hv.y, a.y, acc0);
                acc0 = fmaf(hv.z, a.z, acc0); acc0 = fmaf(hv.w, a.w, acc0);
                acc1 = fmaf(hv.x, f.x, acc1); acc1 = fmaf(hv.y, f.y, acc1);
                acc1 = fmaf(hv.z, f.z, acc1); acc1 = fmaf(hv.w, f.w, acc1);
                acc2 = fmaf(hv.x, g.x, acc2); acc2 = fmaf(hv.y, g.y, acc2);
                acc2 = fmaf(hv.z, g.z, acc2); acc2 = fmaf(hv.w, g.w, acc2);
                acc3 = fmaf(hv.x, o.x, acc3); acc3 = fmaf(hv.y, o.y, acc3);
                acc3 = fmaf(hv.z, o.z, acc3); acc3 = fmaf(hv.w, o.w, acc3);
            }
            __syncthreads();   // hs reused next step; don't let laggards overwrite
        }

        const float* gxr = g_gx + ((size_t)b * NSEG + s) * G4;
        float gi = gxr[n]          + acc0;
        float gf = gxr[NH + n]     + acc1;
        float gg = gxr[2 * NH + n] + acc2;
        float go = gxr[3 * NH + n] + acc3;

        gi = 1.0f / (1.0f + expf(-gi));
        gf = 1.0f / (1.0f + expf(-gf));
        gg = tanhf(gg);
        go = 1.0f / (1.0f + expf(-go));

        float cn = gf * cc + gi * gg;
        float hn = go * tanhf(cn);
        cc = cn;

        g_hbuf[s & 1][b * NH + n] = hn;
        out[((size_t)b * NSEG + s) * NH + n] = hn;

        // grid barrier: all h(s) writes visible before any block starts s+1
        if (s < NSEG - 1) {
            __threadfence();
            __syncthreads();
            if (tid == 0) {
                atomicAdd(&g_bar[s], 1u);
                while (atomicAdd(&g_bar[s], 0u) < NBLK) { }
            }
            __syncthreads();
        }
    }
}

// ============================================================
extern "C" void kernel_launch(void* const* d_in, const int* in_sizes, int n_in,
                              void* d_out, int out_size) {
    const float* x    = (const float*)d_in[0];
    const float* w_ih = (const float*)d_in[1];
    const float* w_hh = (const float*)d_in[2];
    const float* b_ih = (const float*)d_in[3];
    const float* b_hh = (const float*)d_in[4];
    float* out = (float*)d_out;

    // Replicate np.linspace(1,600,51) + round-half-even exactly.
    SegArgs seg;
    const double step = 599.0 / 50.0;
    int tv[NSEG + 1];
    for (int i = 0; i <= NSEG; i++)
        tv[i] = (int)nearbyint(1.0 + step * (double)i);
    tv[NSEG] = TLEN;
    for (int s = 0; s < NSEG; s++) {
        seg.start[s] = tv[s] - 1;
        int len = tv[s + 1] - tv[s];
        if (len > 16) len = 16;
        seg.len[s] = len;
    }

    size_t smem_bytes = (4 * NU * NH + BATCH * HS) * sizeof(float);
    cudaFuncSetAttribute(k_lstm_persist,
                         cudaFuncAttributeMaxDynamicSharedMemorySize,
                         (int)smem_bytes);

    k_reset<<<1, 64>>>();
    k_feats<<<MROWS, 256>>>(x, seg);

    dim3 g2(G4 / BN, MROWS / BM);  // 32 x 25
    k_gemm_gx<<<g2, 256>>>(w_ih, b_ih, b_hh);

    k_lstm_persist<<<NBLK, NBLK, smem_bytes>>>(w_hh, out);
}

// round 4
// speedup vs baseline: 3.4508x; 1.2339x over previous
#include <cuda_runtime.h>
#include <math.h>

#define BATCH 32
#define TLEN  600
#define CH    64
#define NSEG  50
#define NH    512
#define NPAIR (CH*(CH-1)/2)      // 2016
#define LOGSIG_CH (CH + NPAIR)   // 2080
#define INSZ  (LOGSIG_CH + CH)   // 2144
#define G4    (4*NH)             // 2048
#define MROWS (BATCH*NSEG)       // 1600

#define LBLK  128                // persistent LSTM blocks (all resident)
#define LTHR  256

typedef unsigned long long ull;

// ---- scratch (no allocations allowed) ----
__device__ float g_feats[MROWS * INSZ];     // 13.7 MB
__device__ float g_gx[MROWS * G4];          // 13.1 MB
__device__ float g_hbuf[2][BATCH * NH];
__device__ unsigned int g_bar[NSEG];

struct SegArgs { int start[NSEG]; int len[NSEG]; };

// packed fp32x2 FMA (sm_100+; 2x scalar FFMA throughput)
__device__ __forceinline__ void fma2(ull& d, ull a, ull b) {
    asm("fma.rn.f32x2 %0, %1, %2, %0;" : "+l"(d) : "l"(a), "l"(b));
}
__device__ __forceinline__ ull packdup(float x) {
    ull r; unsigned u = __float_as_uint(x);
    asm("mov.b64 %0, {%1, %1};" : "=l"(r) : "r"(u));
    return r;
}
__device__ __forceinline__ float2 unpk(ull v) {
    float2 r;
    asm("mov.b64 {%0, %1}, %2;" : "=f"(r.x), "=f"(r.y) : "l"(v));
    return r;
}

// ============================================================
// Kernel 0: reset grid-barrier counters (graph replays reuse them)
// ============================================================
__global__ void k_reset() {
    int i = threadIdx.x;
    if (i < NSEG) g_bar[i] = 0u;
}

// ============================================================
// Kernel 1: per-(batch,segment) depth-2 log-signature features
// ============================================================
__global__ void k_feats(const float* __restrict__ x, SegArgs seg) {
    int bs = blockIdx.x;
    int b = bs / NSEG, s = bs % NSEG;
    int st = seg.start[s], len = seg.len[s];   // len <= 16

    __shared__ float xs[17][CH];
    const float* xp = x + ((size_t)b * TLEN + st) * CH;
    for (int idx = threadIdx.x; idx < (len + 1) * CH; idx += blockDim.x)
        xs[idx >> 6][idx & 63] = xp[idx];
    __syncthreads();

    float* fr = g_feats + (size_t)bs * INSZ;

    if (threadIdx.x < CH) {
        int c = threadIdx.x;
        float xa = xs[0][c], xe = xs[len][c];
        fr[c] = xe - xa;             // inc
        fr[LOGSIG_CH + c] = xa;      // start point
    }

    for (int p = threadIdx.x; p < NPAIR; p += blockDim.x) {
        int i = 0, rem = p;
        while (rem >= (CH - 1 - i)) { rem -= (CH - 1 - i); i++; }
        int j = i + 1 + rem;

        float acc = 0.0f;
        for (int t = 0; t < len; t++)
            acc += xs[t][i] * xs[t + 1][j] - xs[t][j] * xs[t + 1][i];

        float xai = xs[0][i], xaj = xs[0][j];
        float inci = xs[len][i] - xai;
        float incj = xs[len][j] - xaj;
        fr[CH + p] = 0.5f * (acc - xai * incj + xaj * inci);
    }
}

// ============================================================
// Kernel 2: gx = feats @ w_ih^T + (b_ih + b_hh)
//   M=1600(pad 1664), N=2048, K=2144 (NT).
//   128x64 tile, BK=16, 128 threads, 8x8 microtile, f32x2 FMAs.
// ============================================================
#define GBM 128
#define GBN 64
#define GBK 16

__global__ __launch_bounds__(128)
void k_gemm_gx(const float* __restrict__ w_ih,
               const float* __restrict__ b_ih,
               const float* __restrict__ b_hh) {
    __shared__ __align__(16) float As[GBK][GBM];   // 8KB
    __shared__ __align__(16) float Bs[GBK][GBN];   // 4KB

    int t = threadIdx.x;
    int m0 = blockIdx.y * GBM;
    int n0 = blockIdx.x * GBN;

    // A loader: thread t owns global row m0+t (clamped), 16 k per iter
    int mrow = m0 + t; if (mrow > MROWS - 1) mrow = MROWS - 1;
    const float* Ap = g_feats + (size_t)mrow * INSZ;
    // B loader: thread t owns row n0 + t/2, k-half (t&1)*8
    const float* Bp = w_ih + (size_t)(n0 + (t >> 1)) * INSZ + (t & 1) * 8;

    int tm = (t & 15) * 8;     // 8 output rows
    int tn = (t >> 4) * 8;     // 8 output cols (4 f32x2 pairs)

    ull acc[8][4];
    #pragma unroll
    for (int i = 0; i < 8; i++)
        #pragma unroll
        for (int j = 0; j < 4; j++) acc[i][j] = 0ull;

    for (int k0 = 0; k0 < INSZ; k0 += GBK) {
        float4 a0 = *(const float4*)(Ap + k0);
        float4 a1 = *(const float4*)(Ap + k0 + 4);
        float4 a2 = *(const float4*)(Ap + k0 + 8);
        float4 a3 = *(const float4*)(Ap + k0 + 12);
        float4 bv0 = *(const float4*)(Bp + k0);
        float4 bv1 = *(const float4*)(Bp + k0 + 4);
        __syncthreads();
        As[ 0][t] = a0.x; As[ 1][t] = a0.y; As[ 2][t] = a0.z; As[ 3][t] = a0.w;
        As[ 4][t] = a1.x; As[ 5][t] = a1.y; As[ 6][t] = a1.z; As[ 7][t] = a1.w;
        As[ 8][t] = a2.x; As[ 9][t] = a2.y; As[10][t] = a2.z; As[11][t] = a2.w;
        As[12][t] = a3.x; As[13][t] = a3.y; As[14][t] = a3.z; As[15][t] = a3.w;
        {
            int kb = (t & 1) * 8, rb = t >> 1;
            Bs[kb + 0][rb] = bv0.x; Bs[kb + 1][rb] = bv0.y;
            Bs[kb + 2][rb] = bv0.z; Bs[kb + 3][rb] = bv0.w;
            Bs[kb + 4][rb] = bv1.x; Bs[kb + 5][rb] = bv1.y;
            Bs[kb + 6][rb] = bv1.z; Bs[kb + 7][rb] = bv1.w;
        }
        __syncthreads();

        #pragma unroll
        for (int kk = 0; kk < GBK; kk++) {
            float4 aA = *(const float4*)&As[kk][tm];
            float4 aB = *(const float4*)&As[kk][tm + 4];
            ulonglong2 b01 = *(const ulonglong2*)&Bs[kk][tn];
            ulonglong2 b23 = *(const ulonglong2*)&Bs[kk][tn + 4];
            float av[8] = {aA.x, aA.y, aA.z, aA.w, aB.x, aB.y, aB.z, aB.w};
            #pragma unroll
            for (int i = 0; i < 8; i++) {
                ull ad = packdup(av[i]);
                fma2(acc[i][0], ad, b01.x);
                fma2(acc[i][1], ad, b01.y);
                fma2(acc[i][2], ad, b23.x);
                fma2(acc[i][3], ad, b23.y);
            }
        }
    }

    float bias[8];
    #pragma unroll
    for (int j = 0; j < 8; j++) {
        int n = n0 + tn + j;
        bias[j] = b_ih[n] + b_hh[n];
    }
    #pragma unroll
    for (int i = 0; i < 8; i++) {
        int m = m0 + tm + i;
        if (m < MROWS) {
            float* orow = g_gx + (size_t)m * G4 + n0 + tn;
            #pragma unroll
            for (int j = 0; j < 4; j++) {
                float2 v = unpk(acc[i][j]);
                orow[2 * j]     = v.x + bias[2 * j];
                orow[2 * j + 1] = v.y + bias[2 * j + 1];
            }
        }
    }
}

// ============================================================
// Kernel 3: PERSISTENT LSTM, register-resident h.
//   128 blocks x 256 threads. Block owns 4 hidden units
//   (16 gate-rows of w_hh, 32KB in SMEM, loaded once).
//   Warp w owns k-window [w*64, w*64+64); lane = batch.
//   h(s-1)[b][k-window] lives in 32 f32x2 registers per lane.
//   Weight reads are warp-uniform LDS.128 broadcasts; all FMAs
//   are fma.rn.f32x2. Partials reduced via SMEM; c in registers
//   of threads 0..127. Grid spin-barrier between steps.
// ============================================================
__global__ __launch_bounds__(LTHR, 1)
void k_lstm_persist(const float* __restrict__ whh,
                    float* __restrict__ out) {
    __shared__ float ws[16 * NH];        // 32 KB
    __shared__ float ps[8 * 16 * 32];    // 16 KB partials [w][row][b]

    int tid  = threadIdx.x;
    int warp = tid >> 5;
    int lane = tid & 31;
    int n0 = blockIdx.x * 4;             // 4 hidden units
    int kw = warp * 64;                  // this warp's k-window

    // Load w_hh slice once: row r = g*4+u  ->  whh[(g*NH + n0+u)*NH + k]
    for (int i = tid; i < 16 * (NH / 4); i += LTHR) {
        int r = i >> 7, kq = i & 127;
        int g = r >> 2, u = r & 3;
        ((float4*)ws)[r * (NH / 4) + kq] =
            ((const float4*)(whh + ((size_t)g * NH + n0 + u) * NH))[kq];
    }
    __syncthreads();

    // cell state for update threads (tid<128): u = tid>>5, b = tid&31
    float cc = 0.0f;
    int ub_u = tid >> 5;                 // valid when tid<128
    int ub_b = tid & 31;

    ull hreg[32];                        // h[lane][kw..kw+64) as 32 f32x2
    #pragma unroll
    for (int i = 0; i < 32; i++) hreg[i] = 0ull;

    for (int s = 0; s < NSEG; s++) {
        if (s > 0) {
            // ---- matvec partials: acc2[r] = sum_k w[r][k]*h[b][k] over k-window
            ull acc2[16];
            #pragma unroll
            for (int r = 0; r < 16; r++) acc2[r] = 0ull;

            #pragma unroll
            for (int kk4 = 0; kk4 < 16; kk4++) {
                ull h0 = hreg[2 * kk4], h1 = hreg[2 * kk4 + 1];
                #pragma unroll
                for (int r = 0; r < 16; r++) {
                    ulonglong2 wv = *(const ulonglong2*)&ws[r * NH + kw + kk4 * 4];
                    fma2(acc2[r], wv.x, h0);
                    fma2(acc2[r], wv.y, h1);
                }
            }
            #pragma unroll
            for (int r = 0; r < 16; r++) {
                float2 v = unpk(acc2[r]);
                ps[(warp * 16 + r) * 32 + lane] = v.x + v.y;
            }
        }
        __syncthreads();

        // ---- cell update (threads 0..127): thread (u,b)
        if (tid < 128) {
            int b = ub_b, u = ub_u;
            const float* gxr = g_gx + ((size_t)b * NSEG + s) * G4;
            float gsum[4];
            #pragma unroll
            for (int g = 0; g < 4; g++) {
                float a = gxr[g * NH + n0 + u];
                if (s > 0) {
                    int row = g * 4 + u;
                    #pragma unroll
                    for (int w = 0; w < 8; w++)
                        a += ps[(w * 16 + row) * 32 + b];
                }
                gsum[g] = a;
            }
            float gi = 1.0f / (1.0f + expf(-gsum[0]));
            float gf = 1.0f / (1.0f + expf(-gsum[1]));
            float gg = tanhf(gsum[2]);
            float go = 1.0f / (1.0f + expf(-gsum[3]));

            float cn = gf * cc + gi * gg;
            float hn = go * tanhf(cn);
            cc = cn;

            g_hbuf[s & 1][b * NH + n0 + u] = hn;
            out[((size_t)b * NSEG + s) * NH + n0 + u] = hn;
        }

        if (s < NSEG - 1) {
            // ---- grid barrier: all h(s) visible before anyone reads
            __threadfence();
            __syncthreads();
            if (tid == 0) {
                atomicAdd(&g_bar[s], 1u);
                while (atomicAdd(&g_bar[s], 0u) < LBLK) { }
            }
            __syncthreads();

            // ---- reload this lane's h window (L2-coherent; L1 may be stale)
            const double2* src = (const double2*)(g_hbuf[s & 1] + lane * NH + kw);
            #pragma unroll
            for (int i = 0; i < 16; i++) {
                double2 v = __ldcg(src + i);
                hreg[2 * i]     = (ull)__double_as_longlong(v.x);
                hreg[2 * i + 1] = (ull)__double_as_longlong(v.y);
            }
        }
    }
}

// ============================================================
extern "C" void kernel_launch(void* const* d_in, const int* in_sizes, int n_in,
                              void* d_out, int out_size) {
    const float* x    = (const float*)d_in[0];
    const float* w_ih = (const float*)d_in[1];
    const float* w_hh = (const float*)d_in[2];
    const float* b_ih = (const float*)d_in[3];
    const float* b_hh = (const float*)d_in[4];
    float* out = (float*)d_out;

    // Replicate np.linspace(1,600,51) + round-half-even exactly.
    SegArgs seg;
    const double step = 599.0 / 50.0;
    int tv[NSEG + 1];
    for (int i = 0; i <= NSEG; i++)
        tv[i] = (int)nearbyint(1.0 + step * (double)i);
    tv[NSEG] = TLEN;
    for (int s = 0; s < NSEG; s++) {
        seg.start[s] = tv[s] - 1;
        int len = tv[s + 1] - tv[s];
        if (len > 16) len = 16;
        seg.len[s] = len;
    }

    k_reset<<<1, 64>>>();
    k_feats<<<MROWS, 256>>>(x, seg);

    dim3 g2(G4 / GBN, (MROWS + GBM - 1) / GBM);   // 32 x 13
    k_gemm_gx<<<g2, 128>>>(w_ih, b_ih, b_hh);

    k_lstm_persist<<<LBLK, LTHR>>>(w_hh, out);
}

// round 5
// speedup vs baseline: 3.8702x; 1.1216x over previous
#include <cuda_runtime.h>
#include <math.h>

#define BATCH 32
#define TLEN  600
#define CH    64
#define NSEG  50
#define NH    512
#define NPAIR (CH*(CH-1)/2)      // 2016
#define LOGSIG_CH (CH + NPAIR)   // 2080
#define INSZ  (LOGSIG_CH + CH)   // 2144
#define G4    (4*NH)             // 2048
#define MROWS (BATCH*NSEG)       // 1600

#define LBLK  128                // persistent LSTM blocks (all resident)
#define LTHR  256

typedef unsigned long long ull;

// ---- scratch (no allocations allowed) ----
__device__ float g_feats[MROWS * INSZ];     // 13.7 MB
__device__ float g_gx[MROWS * G4];          // 13.1 MB
__device__ float g_hbuf[2][BATCH * NH];
__device__ unsigned int g_bar[NSEG];

struct SegArgs { int start[NSEG]; int len[NSEG]; };

// packed fp32x2 FMA (sm_100+; 2x scalar FFMA throughput)
__device__ __forceinline__ void fma2(ull& d, ull a, ull b) {
    asm("fma.rn.f32x2 %0, %1, %2, %0;" : "+l"(d) : "l"(a), "l"(b));
}
__device__ __forceinline__ ull packdup(float x) {
    ull r; unsigned u = __float_as_uint(x);
    asm("mov.b64 %0, {%1, %1};" : "=l"(r) : "r"(u));
    return r;
}
__device__ __forceinline__ float2 unpk(ull v) {
    float2 r;
    asm("mov.b64 {%0, %1}, %2;" : "=f"(r.x), "=f"(r.y) : "l"(v));
    return r;
}

// ============================================================
// Kernel 0: reset grid-barrier counters (graph replays reuse them)
// ============================================================
__global__ void k_reset() {
    int i = threadIdx.x;
    if (i < NSEG) g_bar[i] = 0u;
}

// ============================================================
// Kernel 1: per-(batch,segment) depth-2 log-signature features
// ============================================================
__global__ void k_feats(const float* __restrict__ x, SegArgs seg) {
    int bs = blockIdx.x;
    int b = bs / NSEG, s = bs % NSEG;
    int st = seg.start[s], len = seg.len[s];   // len <= 16

    __shared__ float xs[17][CH];
    const float* xp = x + ((size_t)b * TLEN + st) * CH;
    for (int idx = threadIdx.x; idx < (len + 1) * CH; idx += blockDim.x)
        xs[idx >> 6][idx & 63] = xp[idx];
    __syncthreads();

    float* fr = g_feats + (size_t)bs * INSZ;

    if (threadIdx.x < CH) {
        int c = threadIdx.x;
        float xa = xs[0][c], xe = xs[len][c];
        fr[c] = xe - xa;             // inc
        fr[LOGSIG_CH + c] = xa;      // start point
    }

    for (int p = threadIdx.x; p < NPAIR; p += blockDim.x) {
        int i = 0, rem = p;
        while (rem >= (CH - 1 - i)) { rem -= (CH - 1 - i); i++; }
        int j = i + 1 + rem;

        float acc = 0.0f;
        for (int t = 0; t < len; t++)
            acc += xs[t][i] * xs[t + 1][j] - xs[t][j] * xs[t + 1][i];

        float xai = xs[0][i], xaj = xs[0][j];
        float inci = xs[len][i] - xai;
        float incj = xs[len][j] - xaj;
        fr[CH + p] = 0.5f * (acc - xai * incj + xaj * inci);
    }
}

// ============================================================
// Kernel 2: gx = feats @ w_ih^T + (b_ih + b_hh)
//   M=1600, N=2048, K=2144 (NT). 64x64 tile, BK=16, 128 thr,
//   4x8 f32x2 microtile, register-prefetch pipeline.
//   Grid 32x25 = 800 tiles (exact; fine wave balance).
// ============================================================
#define GBM 64
#define GBN 64
#define GBK 16

__global__ __launch_bounds__(128, 6)
void k_gemm_gx(const float* __restrict__ w_ih,
               const float* __restrict__ b_ih,
               const float* __restrict__ b_hh) {
    __shared__ __align__(16) float As[GBK][GBM];   // 4KB
    __shared__ __align__(16) float Bs[GBK][GBN];   // 4KB

    int t = threadIdx.x;
    int m0 = blockIdx.y * GBM;
    int n0 = blockIdx.x * GBN;

    // loader: thread t owns row t>>1 of the tile, k-half (t&1)*8
    int lrow = t >> 1;
    int lk = (t & 1) * 8;
    const float* Ap = g_feats + (size_t)(m0 + lrow) * INSZ + lk;
    const float* Bp = w_ih    + (size_t)(n0 + lrow) * INSZ + lk;

    int tm = (t & 15) * 4;     // 4 output rows
    int tn = (t >> 4) * 8;     // 8 output cols (4 f32x2 pairs)

    ull acc[4][4];
    #pragma unroll
    for (int i = 0; i < 4; i++)
        #pragma unroll
        for (int j = 0; j < 4; j++) acc[i][j] = 0ull;

    // prologue prefetch (tile 0)
    float4 pa0 = *(const float4*)(Ap);
    float4 pa1 = *(const float4*)(Ap + 4);
    float4 pb0 = *(const float4*)(Bp);
    float4 pb1 = *(const float4*)(Bp + 4);

    for (int k0 = 0; k0 < INSZ; k0 += GBK) {
        // store prefetched tile
        As[lk + 0][lrow] = pa0.x; As[lk + 1][lrow] = pa0.y;
        As[lk + 2][lrow] = pa0.z; As[lk + 3][lrow] = pa0.w;
        As[lk + 4][lrow] = pa1.x; As[lk + 5][lrow] = pa1.y;
        As[lk + 6][lrow] = pa1.z; As[lk + 7][lrow] = pa1.w;
        Bs[lk + 0][lrow] = pb0.x; Bs[lk + 1][lrow] = pb0.y;
        Bs[lk + 2][lrow] = pb0.z; Bs[lk + 3][lrow] = pb0.w;
        Bs[lk + 4][lrow] = pb1.x; Bs[lk + 5][lrow] = pb1.y;
        Bs[lk + 6][lrow] = pb1.z; Bs[lk + 7][lrow] = pb1.w;
        __syncthreads();

        // prefetch next tile (overlaps compute); wrap harmlessly on last
        int kn = k0 + GBK; if (kn >= INSZ) kn = 0;
        pa0 = *(const float4*)(Ap + kn);
        pa1 = *(const float4*)(Ap + kn + 4);
        pb0 = *(const float4*)(Bp + kn);
        pb1 = *(const float4*)(Bp + kn + 4);

        #pragma unroll
        for (int kk = 0; kk < GBK; kk++) {
            float4 a4 = *(const float4*)&As[kk][tm];
            ulonglong2 b01 = *(const ulonglong2*)&Bs[kk][tn];
            ulonglong2 b23 = *(const ulonglong2*)&Bs[kk][tn + 4];
            float av[4] = {a4.x, a4.y, a4.z, a4.w};
            #pragma unroll
            for (int i = 0; i < 4; i++) {
                ull ad = packdup(av[i]);
                fma2(acc[i][0], ad, b01.x);
                fma2(acc[i][1], ad, b01.y);
                fma2(acc[i][2], ad, b23.x);
                fma2(acc[i][3], ad, b23.y);
            }
        }
        __syncthreads();
    }

    float bias[8];
    #pragma unroll
    for (int j = 0; j < 8; j++) {
        int n = n0 + tn + j;
        bias[j] = b_ih[n] + b_hh[n];
    }
    #pragma unroll
    for (int i = 0; i < 4; i++) {
        float* orow = g_gx + (size_t)(m0 + tm + i) * G4 + n0 + tn;
        #pragma unroll
        for (int j = 0; j < 4; j++) {
            float2 v = unpk(acc[i][j]);
            orow[2 * j]     = v.x + bias[2 * j];
            orow[2 * j + 1] = v.y + bias[2 * j + 1];
        }
    }
}

// ============================================================
// Kernel 3: PERSISTENT LSTM, register-resident h.
//   128 blocks x 256 threads. Block owns 4 hidden units
//   (16 gate-rows of w_hh, 32KB SMEM, loaded once).
//   Warp w owns k-window [w*64, w*64+64); lane = batch.
//   Grid barrier: red.release arrival + ld.acquire load-poll.
//   gx for step s+1 prefetched into regs before the barrier.
// ============================================================
__global__ __launch_bounds__(LTHR, 1)
void k_lstm_persist(const float* __restrict__ whh,
                    float* __restrict__ out) {
    __shared__ float ws[16 * NH];        // 32 KB
    __shared__ float ps[8 * 16 * 32];    // 16 KB partials [w][row][b]

    int tid  = threadIdx.x;
    int warp = tid >> 5;
    int lane = tid & 31;
    int n0 = blockIdx.x * 4;             // 4 hidden units
    int kw = warp * 64;                  // this warp's k-window

    // Load w_hh slice once: row r = g*4+u  ->  whh[(g*NH + n0+u)*NH + k]
    for (int i = tid; i < 16 * (NH / 4); i += LTHR) {
        int r = i >> 7, kq = i & 127;
        int g = r >> 2, u = r & 3;
        ((float4*)ws)[r * (NH / 4) + kq] =
            ((const float4*)(whh + ((size_t)g * NH + n0 + u) * NH))[kq];
    }
    __syncthreads();

    float cc = 0.0f;
    int ub_u = tid >> 5;                 // valid when tid<128
    int ub_b = tid & 31;

    ull hreg[32];                        // h[lane][kw..kw+64) as 32 f32x2
    #pragma unroll
    for (int i = 0; i < 32; i++) hreg[i] = 0ull;

    // prefetch gx for step 0
    float pgx[4];
    if (tid < 128) {
        const float* gxr = g_gx + (size_t)ub_b * NSEG * G4;
        #pragma unroll
        for (int g = 0; g < 4; g++)
            pgx[g] = gxr[g * NH + n0 + ub_u];
    }

    for (int s = 0; s < NSEG; s++) {
        if (s > 0) {
            // ---- matvec partials over this warp's k-window
            ull acc2[16];
            #pragma unroll
            for (int r = 0; r < 16; r++) acc2[r] = 0ull;

            #pragma unroll
            for (int kk4 = 0; kk4 < 16; kk4++) {
                ull h0 = hreg[2 * kk4], h1 = hreg[2 * kk4 + 1];
                #pragma unroll
                for (int r = 0; r < 16; r++) {
                    ulonglong2 wv = *(const ulonglong2*)&ws[r * NH + kw + kk4 * 4];
                    fma2(acc2[r], wv.x, h0);
                    fma2(acc2[r], wv.y, h1);
                }
            }
            #pragma unroll
            for (int r = 0; r < 16; r++) {
                float2 v = unpk(acc2[r]);
                ps[(warp * 16 + r) * 32 + lane] = v.x + v.y;
            }
        }
        __syncthreads();

        // ---- cell update (threads 0..127): thread (u,b)
        if (tid < 128) {
            int b = ub_b, u = ub_u;
            float gsum[4];
            #pragma unroll
            for (int g = 0; g < 4; g++) {
                float a = pgx[g];
                if (s > 0) {
                    int row = g * 4 + u;
                    #pragma unroll
                    for (int w = 0; w < 8; w++)
                        a += ps[(w * 16 + row) * 32 + b];
                }
                gsum[g] = a;
            }
            float gi = 1.0f / (1.0f + expf(-gsum[0]));
            float gf = 1.0f / (1.0f + expf(-gsum[1]));
            float gg = tanhf(gsum[2]);
            float go = 1.0f / (1.0f + expf(-gsum[3]));

            float cn = gf * cc + gi * gg;
            float hn = go * tanhf(cn);
            cc = cn;

            g_hbuf[s & 1][b * NH + n0 + u] = hn;
            out[((size_t)b * NSEG + s) * NH + n0 + u] = hn;
        }

        if (s < NSEG - 1) {
            // ---- prefetch gx(s+1): independent of barrier, hides L2 latency
            if (tid < 128) {
                const float* gxr = g_gx + ((size_t)ub_b * NSEG + s + 1) * G4;
                #pragma unroll
                for (int g = 0; g < 4; g++)
                    pgx[g] = gxr[g * NH + n0 + ub_u];
            }

            // ---- grid barrier
            __threadfence();
            __syncthreads();
            if (tid == 0) {
                asm volatile("red.release.gpu.global.add.u32 [%0], 1;"
                             :: "l"(&g_bar[s]) : "memory");
                unsigned v;
                do {
                    asm volatile("ld.acquire.gpu.global.u32 %0, [%1];"
                                 : "=r"(v) : "l"(&g_bar[s]) : "memory");
                } while (v < LBLK);
            }
            __syncthreads();

            // ---- reload this lane's h window (L2-coherent)
            const double2* src = (const double2*)(g_hbuf[s & 1] + lane * NH + kw);
            #pragma unroll
            for (int i = 0; i < 16; i++) {
                double2 v = __ldcg(src + i);
                hreg[2 * i]     = (ull)__double_as_longlong(v.x);
                hreg[2 * i + 1] = (ull)__double_as_longlong(v.y);
            }
        }
    }
}

// ============================================================
extern "C" void kernel_launch(void* const* d_in, const int* in_sizes, int n_in,
                              void* d_out, int out_size) {
    const float* x    = (const float*)d_in[0];
    const float* w_ih = (const float*)d_in[1];
    const float* w_hh = (const float*)d_in[2];
    const float* b_ih = (const float*)d_in[3];
    const float* b_hh = (const float*)d_in[4];
    float* out = (float*)d_out;

    // Replicate np.linspace(1,600,51) + round-half-even exactly.
    SegArgs seg;
    const double step = 599.0 / 50.0;
    int tv[NSEG + 1];
    for (int i = 0; i <= NSEG; i++)
        tv[i] = (int)nearbyint(1.0 + step * (double)i);
    tv[NSEG] = TLEN;
    for (int s = 0; s < NSEG; s++) {
        seg.start[s] = tv[s] - 1;
        int len = tv[s + 1] - tv[s];
        if (len > 16) len = 16;
        seg.len[s] = len;
    }

    k_reset<<<1, 64>>>();
    k_feats<<<MROWS, 256>>>(x, seg);

    dim3 g2(G4 / GBN, MROWS / GBM);   // 32 x 25 = 800 tiles
    k_gemm_gx<<<g2, 128>>>(w_ih, b_ih, b_hh);

    k_lstm_persist<<<LBLK, LTHR>>>(w_hh, out);
}

// round 8
// speedup vs baseline: 5.2747x; 1.3629x over previous
#include <cuda_runtime.h>
#include <cuda_bf16.h>
#include <cstdint>
#include <math.h>

#define BATCH 32
#define TLEN  600
#define CH    64
#define NSEG  50
#define NH    512
#define NPAIR (CH*(CH-1)/2)      // 2016
#define LOGSIG_CH (CH + NPAIR)   // 2080
#define INSZ  (LOGSIG_CH + CH)   // 2144
#define G4    (4*NH)             // 2048
#define MROWS (BATCH*NSEG)       // 1600

#define LBLK  128
#define LTHR  256

// --- HMMA GEMM geometry ---
#define MP   1664                // M padded to 128
#define KP   2176                // K padded to 64
#define NCH  68                  // KP/32 k-chunks
#define SROW 80                  // smem row stride bytes (40 bf16) - conflict-free
#define REG_B 10240              // 128 rows * 80 B per split region
#define STG_B 40960              // 4 regions per stage
#define SM_HMMA (2 * STG_B)      // 81920

typedef unsigned long long ull;

// ---- scratch (no allocations allowed) ----
__device__ float g_feats[MROWS * INSZ];
__device__ float g_gx[MROWS * G4];
__device__ float g_hbuf[2][BATCH * NH];
__device__ unsigned int g_bar[NSEG];
__device__ __nv_bfloat16 g_Ah[MP * KP];
__device__ __nv_bfloat16 g_Al[MP * KP];
__device__ __nv_bfloat16 g_Bh[(size_t)G4 * KP];
__device__ __nv_bfloat16 g_Bl[(size_t)G4 * KP];

struct SegArgs { int start[NSEG]; int len[NSEG]; };

// ================= helpers =================
__device__ __forceinline__ uint32_t smem_u32(const void* p) {
    uint32_t a;
    asm("{ .reg .u64 t; cvta.to.shared.u64 t, %1; cvt.u32.u64 %0, t; }"
        : "=r"(a) : "l"(p));
    return a;
}
__device__ __forceinline__ void ldsm4(uint32_t* r, uint32_t addr) {
    asm volatile("ldmatrix.sync.aligned.m8n8.x4.shared.b16 {%0,%1,%2,%3}, [%4];"
        : "=r"(r[0]), "=r"(r[1]), "=r"(r[2]), "=r"(r[3]) : "r"(addr));
}
__device__ __forceinline__ void mma_bf16(float* d, const uint32_t* a, const uint32_t* b) {
    asm volatile(
        "mma.sync.aligned.m16n8k16.row.col.f32.bf16.bf16.f32 "
        "{%0,%1,%2,%3}, {%4,%5,%6,%7}, {%8,%9}, {%0,%1,%2,%3};"
        : "+f"(d[0]), "+f"(d[1]), "+f"(d[2]), "+f"(d[3])
        : "r"(a[0]), "r"(a[1]), "r"(a[2]), "r"(a[3]), "r"(b[0]), "r"(b[1]));
}
__device__ __forceinline__ void cpa16(uint32_t dst, const void* src) {
    asm volatile("cp.async.cg.shared.global [%0], [%1], 16;" :: "r"(dst), "l"(src));
}
// packed fp32x2 FMA helpers (LSTM)
__device__ __forceinline__ void fma2(ull& d, ull a, ull b) {
    asm("fma.rn.f32x2 %0, %1, %2, %0;" : "+l"(d) : "l"(a), "l"(b));
}
__device__ __forceinline__ float2 unpk(ull v) {
    float2 r;
    asm("mov.b64 {%0, %1}, %2;" : "=f"(r.x), "=f"(r.y) : "l"(v));
    return r;
}

// ============================================================
__global__ void k_reset() {
    int i = threadIdx.x;
    if (i < NSEG) g_bar[i] = 0u;
}

// ============================================================
// Kernel 1: depth-2 log-signature features
// ============================================================
__global__ void k_feats(const float* __restrict__ x, SegArgs seg) {
    int bs = blockIdx.x;
    int b = bs / NSEG, s = bs % NSEG;
    int st = seg.start[s], len = seg.len[s];

    __shared__ float xs[17][CH];
    const float* xp = x + ((size_t)b * TLEN + st) * CH;
    for (int idx = threadIdx.x; idx < (len + 1) * CH; idx += blockDim.x)
        xs[idx >> 6][idx & 63] = xp[idx];
    __syncthreads();

    float* fr = g_feats + (size_t)bs * INSZ;

    if (threadIdx.x < CH) {
        int c = threadIdx.x;
        float xa = xs[0][c], xe = xs[len][c];
        fr[c] = xe - xa;
        fr[LOGSIG_CH + c] = xa;
    }

    for (int p = threadIdx.x; p < NPAIR; p += blockDim.x) {
        int i = 0, rem = p;
        while (rem >= (CH - 1 - i)) { rem -= (CH - 1 - i); i++; }
        int j = i + 1 + rem;

        float acc = 0.0f;
        for (int t = 0; t < len; t++)
            acc += xs[t][i] * xs[t + 1][j] - xs[t][j] * xs[t + 1][i];

        float xai = xs[0][i], xaj = xs[0][j];
        float inci = xs[len][i] - xai;
        float incj = xs[len][j] - xaj;
        fr[CH + p] = 0.5f * (acc - xai * incj + xaj * inci);
    }
}

// ============================================================
// Pack kernels: fp32 -> (hi,lo) bf16 row-major padded arrays
// ============================================================
__device__ __forceinline__ void pack8(const float* v, uint4& h4, uint4& l4) {
    __nv_bfloat16 h[8], l[8];
    #pragma unroll
    for (int i = 0; i < 8; i++) {
        h[i] = __float2bfloat16(v[i]);
        l[i] = __float2bfloat16(v[i] - __bfloat162float(h[i]));
    }
    h4 = *(uint4*)h; l4 = *(uint4*)l;
}

__global__ void k_packA() {   // grid (KP/64=34, MP/128=13), 128 thr
    int kc = blockIdx.x, mt = blockIdx.y;
    for (int u = threadIdx.x; u < 1024; u += 128) {
        int r = u >> 3, cu = u & 7;
        int m = mt * 128 + r, k = kc * 64 + cu * 8;
        float v[8] = {0,0,0,0,0,0,0,0};
        if (m < MROWS && k < INSZ) {
            const float* src = g_feats + (size_t)m * INSZ + k;
            float4 a = *(const float4*)src, b2 = *(const float4*)(src + 4);
            v[0]=a.x; v[1]=a.y; v[2]=a.z; v[3]=a.w;
            v[4]=b2.x; v[5]=b2.y; v[6]=b2.z; v[7]=b2.w;
        }
        uint4 h4, l4; pack8(v, h4, l4);
        size_t o = (size_t)m * KP + k;
        *(uint4*)(g_Ah + o) = h4;
        *(uint4*)(g_Al + o) = l4;
    }
}

__global__ void k_packB(const float* __restrict__ w_ih) {  // grid (34, 16)
    int kc = blockIdx.x, nt = blockIdx.y;
    for (int u = threadIdx.x; u < 1024; u += 128) {
        int r = u >> 3, cu = u & 7;
        int n = nt * 128 + r, k = kc * 64 + cu * 8;
        float v[8] = {0,0,0,0,0,0,0,0};
        if (k < INSZ) {
            const float* src = w_ih + (size_t)n * INSZ + k;
            float4 a = *(const float4*)src, b2 = *(const float4*)(src + 4);
            v[0]=a.x; v[1]=a.y; v[2]=a.z; v[3]=a.w;
            v[4]=b2.x; v[5]=b2.y; v[6]=b2.z; v[7]=b2.w;
        }
        uint4 h4, l4; pack8(v, h4, l4);
        size_t o = (size_t)n * KP + k;
        *(uint4*)(g_Bh + o) = h4;
        *(uint4*)(g_Bl + o) = l4;
    }
}

// ============================================================
// Kernel 2: HMMA GEMM  gx = feats @ w_ih^T + bias
//   split-bf16 (Ah*Bh + Al*Bh + Ah*Bl), mma.sync m16n8k16.
//   128x128 tile, 256 thr (8 warps, 4x2), k-chunk 32,
//   cp.async double-buffered smem, one wave (208 CTAs, 2/SM).
// smem stage regions: Ah | Al | Bh | Bl, each 128 rows x 80 B.
// ============================================================
__global__ __launch_bounds__(256, 2)
void k_hmma(const float* __restrict__ b_ih, const float* __restrict__ b_hh) {
    extern __shared__ __align__(128) char smem[];
    uint32_t sb = smem_u32(smem);

    int tid = threadIdx.x;
    int warp = tid >> 5, lane = tid & 31;
    int nbx = blockIdx.x, mby = blockIdx.y;
    int wm = (warp & 3) * 32;      // warp M offset in tile
    int wn = (warp >> 2) * 64;     // warp N offset in tile

    float acc[2][8][4];
    #pragma unroll
    for (int i = 0; i < 2; i++)
        #pragma unroll
        for (int j = 0; j < 8; j++)
            #pragma unroll
            for (int k = 0; k < 4; k++) acc[i][j][k] = 0.0f;

    // ---- cp.async copy of one k-chunk into a stage ----
    auto issue = [&](int stg, int kc) {
        uint32_t dstb = sb + stg * STG_B;
        #pragma unroll
        for (int i = 0; i < 8; i++) {
            const int region = i >> 1;                 // compile-time
            int rem = tid + (i & 1) * 256;             // 0..511
            int r = rem >> 2, q = rem & 3;
            const __nv_bfloat16* base =
                (region == 0) ? g_Ah : (region == 1) ? g_Al :
                (region == 2) ? g_Bh : g_Bl;
            size_t row = (region < 2) ? (size_t)(mby * 128 + r)
                                      : (size_t)(nbx * 128 + r);
            const void* gp = base + row * KP + kc * 32 + q * 8;
            cpa16(dstb + region * REG_B + r * SROW + q * 16, gp);
        }
        asm volatile("cp.async.commit_group;");
    };

    issue(0, 0);

    // ---- ldmatrix lane addressing (constant per thread) ----
    uint32_t a_row = lane & 15;
    uint32_t a_colq = (lane >> 4) * 8;                   // 0 or 8
    uint32_t b_n = ((lane >> 4) & 1) * 8 + (lane & 7);
    uint32_t b_kq = ((lane >> 3) & 1) * 8;               // 0 or 8

    for (int kc = 0; kc < NCH; kc++) {
        int s = kc & 1;
        asm volatile("cp.async.wait_group 0;" ::: "memory");
        __syncthreads();
        if (kc + 1 < NCH) issue(s ^ 1, kc + 1);

        uint32_t stb = sb + s * STG_B;
        #pragma unroll
        for (int k16 = 0; k16 < 32; k16 += 16) {
            uint32_t ah[2][4], al[2][4], bb[8][2];
            #pragma unroll
            for (int mt = 0; mt < 2; mt++) {
                uint32_t ad = stb + (wm + mt * 16 + a_row) * SROW
                            + (a_colq + k16) * 2;
                ldsm4(ah[mt], ad);
                ldsm4(al[mt], ad + REG_B);
            }
            uint32_t bkoff = (k16 + b_kq) * 2;
            // B hi
            #pragma unroll
            for (int np = 0; np < 4; np++) {
                uint32_t bd = stb + 2 * REG_B
                            + (wn + np * 16 + b_n) * SROW + bkoff;
                ldsm4(&bb[np * 2][0], bd);
            }
            #pragma unroll
            for (int mt = 0; mt < 2; mt++)
                #pragma unroll
                for (int nt = 0; nt < 8; nt++) {
                    mma_bf16(acc[mt][nt], ah[mt], bb[nt]);
                    mma_bf16(acc[mt][nt], al[mt], bb[nt]);
                }
            // B lo
            #pragma unroll
            for (int np = 0; np < 4; np++) {
                uint32_t bd = stb + 3 * REG_B
                            + (wn + np * 16 + b_n) * SROW + bkoff;
                ldsm4(&bb[np * 2][0], bd);
            }
            #pragma unroll
            for (int mt = 0; mt < 2; mt++)
                #pragma unroll
                for (int nt = 0; nt < 8; nt++)
                    mma_bf16(acc[mt][nt], ah[mt], bb[nt]);
        }
        __syncthreads();
    }

    // ---- epilogue ----
    int tr = lane >> 2;
    int tc = (lane & 3) * 2;
    #pragma unroll
    for (int mt = 0; mt < 2; mt++) {
        #pragma unroll
        for (int nt = 0; nt < 8; nt++) {
            int col = nbx * 128 + wn + nt * 8 + tc;
            float bs0 = b_ih[col] + b_hh[col];
            float bs1 = b_ih[col + 1] + b_hh[col + 1];
            int m0 = mby * 128 + wm + mt * 16 + tr;
            float* d = acc[mt][nt];
            if (m0 < MROWS) {
                float2 v = {d[0] + bs0, d[1] + bs1};
                *(float2*)(g_gx + (size_t)m0 * G4 + col) = v;
            }
            if (m0 + 8 < MROWS) {
                float2 v = {d[2] + bs0, d[3] + bs1};
                *(float2*)(g_gx + (size_t)(m0 + 8) * G4 + col) = v;
            }
        }
    }
}

// ============================================================
// Kernel 3: PERSISTENT LSTM (unchanged from R5-passing version)
// ============================================================
__global__ __launch_bounds__(LTHR, 1)
void k_lstm_persist(const float* __restrict__ whh,
                    float* __restrict__ out) {
    __shared__ float ws[16 * NH];
    __shared__ float ps[8 * 16 * 32];

    int tid  = threadIdx.x;
    int warp = tid >> 5;
    int lane = tid & 31;
    int n0 = blockIdx.x * 4;
    int kw = warp * 64;

    for (int i = tid; i < 16 * (NH / 4); i += LTHR) {
        int r = i >> 7, kq = i & 127;
        int g = r >> 2, u = r & 3;
        ((float4*)ws)[r * (NH / 4) + kq] =
            ((const float4*)(whh + ((size_t)g * NH + n0 + u) * NH))[kq];
    }
    __syncthreads();

    float cc = 0.0f;
    int ub_u = tid >> 5;
    int ub_b = tid & 31;

    ull hreg[32];
    #pragma unroll
    for (int i = 0; i < 32; i++) hreg[i] = 0ull;

    float pgx[4];
    if (tid < 128) {
        const float* gxr = g_gx + (size_t)ub_b * NSEG * G4;
        #pragma unroll
        for (int g = 0; g < 4; g++)
            pgx[g] = gxr[g * NH + n0 + ub_u];
    }

    for (int s = 0; s < NSEG; s++) {
        if (s > 0) {
            ull acc2[16];
            #pragma unroll
            for (int r = 0; r < 16; r++) acc2[r] = 0ull;

            #pragma unroll
            for (int kk4 = 0; kk4 < 16; kk4++) {
                ull h0 = hreg[2 * kk4], h1 = hreg[2 * kk4 + 1];
                #pragma unroll
                for (int r = 0; r < 16; r++) {
                    ulonglong2 wv = *(const ulonglong2*)&ws[r * NH + kw + kk4 * 4];
                    fma2(acc2[r], wv.x, h0);
                    fma2(acc2[r], wv.y, h1);
                }
            }
            #pragma unroll
            for (int r = 0; r < 16; r++) {
                float2 v = unpk(acc2[r]);
                ps[(warp * 16 + r) * 32 + lane] = v.x + v.y;
            }
        }
        __syncthreads();

        if (tid < 128) {
            int b = ub_b, u = ub_u;
            float gsum[4];
            #pragma unroll
            for (int g = 0; g < 4; g++) {
                float a = pgx[g];
                if (s > 0) {
                    int row = g * 4 + u;
                    #pragma unroll
                    for (int w = 0; w < 8; w++)
                        a += ps[(w * 16 + row) * 32 + b];
                }
                gsum[g] = a;
            }
            float gi = 1.0f / (1.0f + expf(-gsum[0]));
            float gf = 1.0f / (1.0f + expf(-gsum[1]));
            float gg = tanhf(gsum[2]);
            float go = 1.0f / (1.0f + expf(-gsum[3]));

            float cn = gf * cc + gi * gg;
            float hn = go * tanhf(cn);
            cc = cn;

            g_hbuf[s & 1][b * NH + n0 + u] = hn;
            out[((size_t)b * NSEG + s) * NH + n0 + u] = hn;
        }

        if (s < NSEG - 1) {
            if (tid < 128) {
                const float* gxr = g_gx + ((size_t)ub_b * NSEG + s + 1) * G4;
                #pragma unroll
                for (int g = 0; g < 4; g++)
                    pgx[g] = gxr[g * NH + n0 + ub_u];
            }

            __syncthreads();
            if (tid == 0) {
                asm volatile("red.release.gpu.global.add.u32 [%0], 1;"
                             :: "l"(&g_bar[s]) : "memory");
                unsigned v;
                do {
                    asm volatile("ld.acquire.gpu.global.u32 %0, [%1];"
                                 : "=r"(v) : "l"(&g_bar[s]) : "memory");
                } while (v < LBLK);
            }
            __syncthreads();

            const double2* src = (const double2*)(g_hbuf[s & 1] + lane * NH + kw);
            #pragma unroll
            for (int i = 0; i < 16; i++) {
                double2 v = __ldcg(src + i);
                hreg[2 * i]     = (ull)__double_as_longlong(v.x);
                hreg[2 * i + 1] = (ull)__double_as_longlong(v.y);
            }
        }
    }
}

// ============================================================
extern "C" void kernel_launch(void* const* d_in, const int* in_sizes, int n_in,
                              void* d_out, int out_size) {
    const float* x    = (const float*)d_in[0];
    const float* w_ih = (const float*)d_in[1];
    const float* w_hh = (const float*)d_in[2];
    const float* b_ih = (const float*)d_in[3];
    const float* b_hh = (const float*)d_in[4];
    float* out = (float*)d_out;

    SegArgs seg;
    const double step = 599.0 / 50.0;
    int tv[NSEG + 1];
    for (int i = 0; i <= NSEG; i++)
        tv[i] = (int)nearbyint(1.0 + step * (double)i);
    tv[NSEG] = TLEN;
    for (int s = 0; s < NSEG; s++) {
        seg.start[s] = tv[s] - 1;
        int len = tv[s + 1] - tv[s];
        if (len > 16) len = 16;
        seg.len[s] = len;
    }

    cudaFuncSetAttribute(k_hmma, cudaFuncAttributeMaxDynamicSharedMemorySize, SM_HMMA);

    k_reset<<<1, 64>>>();
    k_feats<<<MROWS, 256>>>(x, seg);
    k_packA<<<dim3(34, 13), 128>>>();
    k_packB<<<dim3(34, 16), 128>>>(w_ih);
    k_hmma<<<dim3(16, 13), 256, SM_HMMA>>>(b_ih, b_hh);
    k_lstm_persist<<<LBLK, LTHR>>>(w_hh, out);
}

// round 9
// speedup vs baseline: 6.4956x; 1.2315x over previous
#include <cuda_runtime.h>
#include <cuda_bf16.h>
#include <cstdint>
#include <math.h>

#define BATCH 32
#define TLEN  600
#define CH    64
#define NSEG  50
#define NH    512
#define NPAIR (CH*(CH-1)/2)      // 2016
#define LOGSIG_CH (CH + NPAIR)   // 2080
#define INSZ  (LOGSIG_CH + CH)   // 2144
#define G4    (4*NH)             // 2048
#define MROWS (BATCH*NSEG)       // 1600

#define LBLK  128
#define LTHR  256

// --- HMMA GEMM geometry ---
#define MP   1664                // M padded to 128
#define KP   2176                // K padded to 64
#define NCH  68                  // KP/32 k-chunks
#define SROW 80                  // smem row stride bytes - conflict-free
#define REG_B 10240              // 128 rows * 80 B per split region
#define STG_B 40960              // 4 regions per stage
#define SM_HMMA (2 * STG_B)      // 81920

typedef unsigned long long ull;

// ---- scratch (no allocations allowed; zero-initialized at load,
//       padded regions never written -> stay zero across replays) ----
__device__ float g_gx[MROWS * G4];
__device__ float g_hP[2][NH * BATCH];       // pair-packed: [(n>>1)*64 + b*2 + (n&1)]
__device__ unsigned int g_bar[NSEG];
__device__ __nv_bfloat16 g_Ah[MP * KP];
__device__ __nv_bfloat16 g_Al[MP * KP];
__device__ __nv_bfloat16 g_Bh[(size_t)G4 * KP];
__device__ __nv_bfloat16 g_Bl[(size_t)G4 * KP];

struct SegArgs { int start[NSEG]; int len[NSEG]; };

// ================= helpers =================
__device__ __forceinline__ uint32_t smem_u32(const void* p) {
    uint32_t a;
    asm("{ .reg .u64 t; cvta.to.shared.u64 t, %1; cvt.u32.u64 %0, t; }"
        : "=r"(a) : "l"(p));
    return a;
}
__device__ __forceinline__ void ldsm4(uint32_t* r, uint32_t addr) {
    asm volatile("ldmatrix.sync.aligned.m8n8.x4.shared.b16 {%0,%1,%2,%3}, [%4];"
        : "=r"(r[0]), "=r"(r[1]), "=r"(r[2]), "=r"(r[3]) : "r"(addr));
}
__device__ __forceinline__ void mma_bf16(float* d, const uint32_t* a, const uint32_t* b) {
    asm volatile(
        "mma.sync.aligned.m16n8k16.row.col.f32.bf16.bf16.f32 "
        "{%0,%1,%2,%3}, {%4,%5,%6,%7}, {%8,%9}, {%0,%1,%2,%3};"
        : "+f"(d[0]), "+f"(d[1]), "+f"(d[2]), "+f"(d[3])
        : "r"(a[0]), "r"(a[1]), "r"(a[2]), "r"(a[3]), "r"(b[0]), "r"(b[1]));
}
__device__ __forceinline__ void cpa16(uint32_t dst, const void* src) {
    asm volatile("cp.async.cg.shared.global [%0], [%1], 16;" :: "r"(dst), "l"(src));
}
__device__ __forceinline__ void fma2(ull& d, ull a, ull b) {
    asm("fma.rn.f32x2 %0, %1, %2, %0;" : "+l"(d) : "l"(a), "l"(b));
}
__device__ __forceinline__ float2 unpk(ull v) {
    float2 r;
    asm("mov.b64 {%0, %1}, %2;" : "=f"(r.x), "=f"(r.y) : "l"(v));
    return r;
}
__device__ __forceinline__ ull pack2(float x, float y) {
    ull r;
    asm("mov.b64 %0, {%1, %2};" : "=l"(r) : "f"(x), "f"(y));
    return r;
}
__device__ __forceinline__ void st_split(__nv_bfloat16* Ah, __nv_bfloat16* Al,
                                         size_t idx, float v) {
    __nv_bfloat16 h = __float2bfloat16(v);
    Ah[idx] = h;
    Al[idx] = __float2bfloat16(v - __bfloat162float(h));
}

// ============================================================
__global__ void k_reset() {
    int i = threadIdx.x;
    if (i < NSEG) g_bar[i] = 0u;
}

// ============================================================
// Kernel 1: depth-2 log-signature features, written DIRECTLY as
// split hi/lo bf16 into the padded GEMM A operand (row m = bs).
// ============================================================
__global__ void k_feats(const float* __restrict__ x, SegArgs seg) {
    int bs = blockIdx.x;
    int b = bs / NSEG, s = bs % NSEG;
    int st = seg.start[s], len = seg.len[s];

    __shared__ float xs[17][CH];
    const float* xp = x + ((size_t)b * TLEN + st) * CH;
    for (int idx = threadIdx.x; idx < (len + 1) * CH; idx += blockDim.x)
        xs[idx >> 6][idx & 63] = xp[idx];
    __syncthreads();

    size_t base = (size_t)bs * KP;

    if (threadIdx.x < CH) {
        int c = threadIdx.x;
        float xa = xs[0][c], xe = xs[len][c];
        st_split(g_Ah, g_Al, base + c, xe - xa);
        st_split(g_Ah, g_Al, base + LOGSIG_CH + c, xa);
    }

    for (int p = threadIdx.x; p < NPAIR; p += blockDim.x) {
        int i = 0, rem = p;
        while (rem >= (CH - 1 - i)) { rem -= (CH - 1 - i); i++; }
        int j = i + 1 + rem;

        float acc = 0.0f;
        for (int t = 0; t < len; t++)
            acc += xs[t][i] * xs[t + 1][j] - xs[t][j] * xs[t + 1][i];

        float xai = xs[0][i], xaj = xs[0][j];
        float inci = xs[len][i] - xai;
        float incj = xs[len][j] - xaj;
        st_split(g_Ah, g_Al, base + CH + p, 0.5f * (acc - xai * incj + xaj * inci));
    }
}

// ============================================================
// Pack B: w_ih fp32 -> (hi,lo) bf16 row-major padded
// ============================================================
__global__ void k_packB(const float* __restrict__ w_ih) {  // grid (34, 16)
    int kc = blockIdx.x, nt = blockIdx.y;
    for (int u = threadIdx.x; u < 1024; u += 128) {
        int r = u >> 3, cu = u & 7;
        int n = nt * 128 + r, k = kc * 64 + cu * 8;
        float v[8] = {0,0,0,0,0,0,0,0};
        if (k < INSZ) {
            const float* src = w_ih + (size_t)n * INSZ + k;
            float4 a = *(const float4*)src, b2 = *(const float4*)(src + 4);
            v[0]=a.x; v[1]=a.y; v[2]=a.z; v[3]=a.w;
            v[4]=b2.x; v[5]=b2.y; v[6]=b2.z; v[7]=b2.w;
        }
        __nv_bfloat16 h[8], l[8];
        #pragma unroll
        for (int i = 0; i < 8; i++) {
            h[i] = __float2bfloat16(v[i]);
            l[i] = __float2bfloat16(v[i] - __bfloat162float(h[i]));
        }
        size_t o = (size_t)n * KP + k;
        *(uint4*)(g_Bh + o) = *(uint4*)h;
        *(uint4*)(g_Bl + o) = *(uint4*)l;
    }
}

// ============================================================
// Kernel 2: HMMA GEMM  gx = feats @ w_ih^T + bias  (unchanged)
// ============================================================
__global__ __launch_bounds__(256, 2)
void k_hmma(const float* __restrict__ b_ih, const float* __restrict__ b_hh) {
    extern __shared__ __align__(128) char smem[];
    uint32_t sb = smem_u32(smem);

    int tid = threadIdx.x;
    int warp = tid >> 5, lane = tid & 31;
    int nbx = blockIdx.x, mby = blockIdx.y;
    int wm = (warp & 3) * 32;
    int wn = (warp >> 2) * 64;

    float acc[2][8][4];
    #pragma unroll
    for (int i = 0; i < 2; i++)
        #pragma unroll
        for (int j = 0; j < 8; j++)
            #pragma unroll
            for (int k = 0; k < 4; k++) acc[i][j][k] = 0.0f;

    auto issue = [&](int stg, int kc) {
        uint32_t dstb = sb + stg * STG_B;
        #pragma unroll
        for (int i = 0; i < 8; i++) {
            const int region = i >> 1;
            int rem = tid + (i & 1) * 256;
            int r = rem >> 2, q = rem & 3;
            const __nv_bfloat16* base =
                (region == 0) ? g_Ah : (region == 1) ? g_Al :
                (region == 2) ? g_Bh : g_Bl;
            size_t row = (region < 2) ? (size_t)(mby * 128 + r)
                                      : (size_t)(nbx * 128 + r);
            const void* gp = base + row * KP + kc * 32 + q * 8;
            cpa16(dstb + region * REG_B + r * SROW + q * 16, gp);
        }
        asm volatile("cp.async.commit_group;");
    };

    issue(0, 0);

    uint32_t a_row = lane & 15;
    uint32_t a_colq = (lane >> 4) * 8;
    uint32_t b_n = ((lane >> 4) & 1) * 8 + (lane & 7);
    uint32_t b_kq = ((lane >> 3) & 1) * 8;

    for (int kc = 0; kc < NCH; kc++) {
        int s = kc & 1;
        asm volatile("cp.async.wait_group 0;" ::: "memory");
        __syncthreads();
        if (kc + 1 < NCH) issue(s ^ 1, kc + 1);

        uint32_t stb = sb + s * STG_B;
        #pragma unroll
        for (int k16 = 0; k16 < 32; k16 += 16) {
            uint32_t ah[2][4], al[2][4], bb[8][2];
            #pragma unroll
            for (int mt = 0; mt < 2; mt++) {
                uint32_t ad = stb + (wm + mt * 16 + a_row) * SROW
                            + (a_colq + k16) * 2;
                ldsm4(ah[mt], ad);
                ldsm4(al[mt], ad + REG_B);
            }
            uint32_t bkoff = (k16 + b_kq) * 2;
            #pragma unroll
            for (int np = 0; np < 4; np++) {
                uint32_t bd = stb + 2 * REG_B
                            + (wn + np * 16 + b_n) * SROW + bkoff;
                ldsm4(&bb[np * 2][0], bd);
            }
            #pragma unroll
            for (int mt = 0; mt < 2; mt++)
                #pragma unroll
                for (int nt = 0; nt < 8; nt++) {
                    mma_bf16(acc[mt][nt], ah[mt], bb[nt]);
                    mma_bf16(acc[mt][nt], al[mt], bb[nt]);
                }
            #pragma unroll
            for (int np = 0; np < 4; np++) {
                uint32_t bd = stb + 3 * REG_B
                            + (wn + np * 16 + b_n) * SROW + bkoff;
                ldsm4(&bb[np * 2][0], bd);
            }
            #pragma unroll
            for (int mt = 0; mt < 2; mt++)
                #pragma unroll
                for (int nt = 0; nt < 8; nt++)
                    mma_bf16(acc[mt][nt], ah[mt], bb[nt]);
        }
        __syncthreads();
    }

    int tr = lane >> 2;
    int tc = (lane & 3) * 2;
    #pragma unroll
    for (int mt = 0; mt < 2; mt++) {
        #pragma unroll
        for (int nt = 0; nt < 8; nt++) {
            int col = nbx * 128 + wn + nt * 8 + tc;
            float bs0 = b_ih[col] + b_hh[col];
            float bs1 = b_ih[col + 1] + b_hh[col + 1];
            int m0 = mby * 128 + wm + mt * 16 + tr;
            float* d = acc[mt][nt];
            if (m0 < MROWS) {
                float2 v = {d[0] + bs0, d[1] + bs1};
                *(float2*)(g_gx + (size_t)m0 * G4 + col) = v;
            }
            if (m0 + 8 < MROWS) {
                float2 v = {d[2] + bs0, d[3] + bs1};
                *(float2*)(g_gx + (size_t)(m0 + 8) * G4 + col) = v;
            }
        }
    }
}

// ============================================================
// Kernel 3: PERSISTENT LSTM with pair-packed transposed h.
//   h exchange layout: float2 hP[n>>1][b] -> fully coalesced
//   producer stores AND consumer reloads (32 LDG.64/thread).
// ============================================================
__global__ __launch_bounds__(LTHR, 1)
void k_lstm_persist(const float* __restrict__ whh,
                    float* __restrict__ out) {
    __shared__ float ws[16 * NH];
    __shared__ float ps[8 * 16 * 32];

    int tid  = threadIdx.x;
    int warp = tid >> 5;
    int lane = tid & 31;
    int n0 = blockIdx.x * 4;
    int kw = warp * 64;

    for (int i = tid; i < 16 * (NH / 4); i += LTHR) {
        int r = i >> 7, kq = i & 127;
        int g = r >> 2, u = r & 3;
        ((float4*)ws)[r * (NH / 4) + kq] =
            ((const float4*)(whh + ((size_t)g * NH + n0 + u) * NH))[kq];
    }
    __syncthreads();

    float cc = 0.0f;
    int ub_u = tid >> 5;
    int ub_b = tid & 31;
    // producer store index for thread (u,b): n = n0+u
    int hidx = ((n0 + ub_u) >> 1) * 64 + ub_b * 2 + ((n0 + ub_u) & 1);

    ull hreg[32];
    #pragma unroll
    for (int i = 0; i < 32; i++) hreg[i] = 0ull;

    float pgx[4];
    if (tid < 128) {
        const float* gxr = g_gx + (size_t)ub_b * NSEG * G4;
        #pragma unroll
        for (int g = 0; g < 4; g++)
            pgx[g] = gxr[g * NH + n0 + ub_u];
    }

    for (int s = 0; s < NSEG; s++) {
        if (s > 0) {
            ull acc2[16];
            #pragma unroll
            for (int r = 0; r < 16; r++) acc2[r] = 0ull;

            #pragma unroll
            for (int kk4 = 0; kk4 < 16; kk4++) {
                ull h0 = hreg[2 * kk4], h1 = hreg[2 * kk4 + 1];
                #pragma unroll
                for (int r = 0; r < 16; r++) {
                    ulonglong2 wv = *(const ulonglong2*)&ws[r * NH + kw + kk4 * 4];
                    fma2(acc2[r], wv.x, h0);
                    fma2(acc2[r], wv.y, h1);
                }
            }
            #pragma unroll
            for (int r = 0; r < 16; r++) {
                float2 v = unpk(acc2[r]);
                ps[(warp * 16 + r) * 32 + lane] = v.x + v.y;
            }
        }
        __syncthreads();

        if (tid < 128) {
            int b = ub_b, u = ub_u;
            float gsum[4];
            #pragma unroll
            for (int g = 0; g < 4; g++) {
                float a = pgx[g];
                if (s > 0) {
                    int row = g * 4 + u;
                    #pragma unroll
                    for (int w = 0; w < 8; w++)
                        a += ps[(w * 16 + row) * 32 + b];
                }
                gsum[g] = a;
            }
            float gi = 1.0f / (1.0f + expf(-gsum[0]));
            float gf = 1.0f / (1.0f + expf(-gsum[1]));
            float gg = tanhf(gsum[2]);
            float go = 1.0f / (1.0f + expf(-gsum[3]));

            float cn = gf * cc + gi * gg;
            float hn = go * tanhf(cn);
            cc = cn;

            g_hP[s & 1][hidx] = hn;
            out[((size_t)b * NSEG + s) * NH + n0 + u] = hn;
        }

        if (s < NSEG - 1) {
            if (tid < 128) {
                const float* gxr = g_gx + ((size_t)ub_b * NSEG + s + 1) * G4;
                #pragma unroll
                for (int g = 0; g < 4; g++)
                    pgx[g] = gxr[g * NH + n0 + ub_u];
            }

            __syncthreads();
            if (tid == 0) {
                asm volatile("red.release.gpu.global.add.u32 [%0], 1;"
                             :: "l"(&g_bar[s]) : "memory");
                unsigned v;
                do {
                    asm volatile("ld.acquire.gpu.global.u32 %0, [%1];"
                                 : "=r"(v) : "l"(&g_bar[s]) : "memory");
                } while (v < LBLK);
            }
            __syncthreads();

            // coalesced reload: thread (warp kw, lane b) reads 32 float2
            const float2* src = (const float2*)g_hP[s & 1] + (kw >> 1) * 32 + lane;
            #pragma unroll
            for (int i = 0; i < 32; i++) {
                float2 v = __ldcg(src + i * 32);
                hreg[i] = pack2(v.x, v.y);
            }
        }
    }
}

// ============================================================
extern "C" void kernel_launch(void* const* d_in, const int* in_sizes, int n_in,
                              void* d_out, int out_size) {
    const float* x    = (const float*)d_in[0];
    const float* w_ih = (const float*)d_in[1];
    const float* w_hh = (const float*)d_in[2];
    const float* b_ih = (const float*)d_in[3];
    const float* b_hh = (const float*)d_in[4];
    float* out = (float*)d_out;

    SegArgs seg;
    const double step = 599.0 / 50.0;
    int tv[NSEG + 1];
    for (int i = 0; i <= NSEG; i++)
        tv[i] = (int)nearbyint(1.0 + step * (double)i);
    tv[NSEG] = TLEN;
    for (int s = 0; s < NSEG; s++) {
        seg.start[s] = tv[s] - 1;
        int len = tv[s + 1] - tv[s];
        if (len > 16) len = 16;
        seg.len[s] = len;
    }

    cudaFuncSetAttribute(k_hmma, cudaFuncAttributeMaxDynamicSharedMemorySize, SM_HMMA);

    k_reset<<<1, 64>>>();
    k_feats<<<MROWS, 256>>>(x, seg);
    k_packB<<<dim3(34, 16), 128>>>(w_ih);
    k_hmma<<<dim3(16, 13), 256, SM_HMMA>>>(b_ih, b_hh);
    k_lstm_persist<<<LBLK, LTHR>>>(w_hh, out);
}

// round 10
// speedup vs baseline: 7.3259x; 1.1278x over previous
#include <cuda_runtime.h>
#include <cuda_fp16.h>
#include <cstdint>
#include <math.h>

#define BATCH 32
#define TLEN  600
#define CH    64
#define NSEG  50
#define NH    512
#define NPAIR (CH*(CH-1)/2)      // 2016
#define LOGSIG_CH (CH + NPAIR)   // 2080
#define INSZ  (LOGSIG_CH + CH)   // 2144
#define G4    (4*NH)             // 2048
#define MROWS (BATCH*NSEG)       // 1600

#define LBLK  128
#define LTHR  256

// --- HMMA GEMM geometry ---
#define MP   1664                // M padded to 128
#define KP   2176                // K padded to 64
#define NCH  68                  // KP/32 k-chunks (split-K: 34 per half)
#define KHALF 34
#define SROW 80                  // smem row stride bytes - conflict-free
#define REG_B 10240              // 128 rows * 80 B per region
#define STG_B (3 * REG_B)        // Ah | Al | Bh
#define SM_HMMA (2 * STG_B)      // 61440

typedef unsigned long long ull;

// ---- scratch (no allocations; zero-init, padded regions never written) ----
__device__ float g_gx [MROWS * G4];         // split-K half 0 (+bias)
__device__ float g_gx2[MROWS * G4];         // split-K half 1
__device__ float g_hP[2][NH * BATCH];       // pair-packed h
__device__ unsigned int g_bar[NSEG];
__device__ __half g_Ah[MP * KP];
__device__ __half g_Al[MP * KP];
__device__ __half g_Bh[(size_t)G4 * KP];

struct SegArgs { int start[NSEG]; int len[NSEG]; };

// ================= helpers =================
__device__ __forceinline__ uint32_t smem_u32(const void* p) {
    uint32_t a;
    asm("{ .reg .u64 t; cvta.to.shared.u64 t, %1; cvt.u32.u64 %0, t; }"
        : "=r"(a) : "l"(p));
    return a;
}
__device__ __forceinline__ void ldsm4(uint32_t* r, uint32_t addr) {
    asm volatile("ldmatrix.sync.aligned.m8n8.x4.shared.b16 {%0,%1,%2,%3}, [%4];"
        : "=r"(r[0]), "=r"(r[1]), "=r"(r[2]), "=r"(r[3]) : "r"(addr));
}
__device__ __forceinline__ void mma_f16(float* d, const uint32_t* a, const uint32_t* b) {
    asm volatile(
        "mma.sync.aligned.m16n8k16.row.col.f32.f16.f16.f32 "
        "{%0,%1,%2,%3}, {%4,%5,%6,%7}, {%8,%9}, {%0,%1,%2,%3};"
        : "+f"(d[0]), "+f"(d[1]), "+f"(d[2]), "+f"(d[3])
        : "r"(a[0]), "r"(a[1]), "r"(a[2]), "r"(a[3]), "r"(b[0]), "r"(b[1]));
}
__device__ __forceinline__ void cpa16(uint32_t dst, const void* src) {
    asm volatile("cp.async.cg.shared.global [%0], [%1], 16;" :: "r"(dst), "l"(src));
}
__device__ __forceinline__ void fma2(ull& d, ull a, ull b) {
    asm("fma.rn.f32x2 %0, %1, %2, %0;" : "+l"(d) : "l"(a), "l"(b));
}
__device__ __forceinline__ float2 unpk(ull v) {
    float2 r;
    asm("mov.b64 {%0, %1}, %2;" : "=f"(r.x), "=f"(r.y) : "l"(v));
    return r;
}
__device__ __forceinline__ ull pack2(float x, float y) {
    ull r;
    asm("mov.b64 %0, {%1, %2};" : "=l"(r) : "f"(x), "f"(y));
    return r;
}
__device__ __forceinline__ void st_splitA(size_t idx, float v) {
    __half h = __float2half_rn(v);
    g_Ah[idx] = h;
    g_Al[idx] = __float2half_rn(v - __half2float(h));
}

// ============================================================
__global__ void k_reset() {
    int i = threadIdx.x;
    if (i < NSEG) g_bar[i] = 0u;
}

// ============================================================
// Kernel 1: log-signature features -> split fp16 A operand
// ============================================================
__global__ void k_feats(const float* __restrict__ x, SegArgs seg) {
    int bs = blockIdx.x;
    int b = bs / NSEG, s = bs % NSEG;
    int st = seg.start[s], len = seg.len[s];

    __shared__ float xs[17][CH];
    const float* xp = x + ((size_t)b * TLEN + st) * CH;
    for (int idx = threadIdx.x; idx < (len + 1) * CH; idx += blockDim.x)
        xs[idx >> 6][idx & 63] = xp[idx];
    __syncthreads();

    size_t base = (size_t)bs * KP;

    if (threadIdx.x < CH) {
        int c = threadIdx.x;
        float xa = xs[0][c], xe = xs[len][c];
        st_splitA(base + c, xe - xa);
        st_splitA(base + LOGSIG_CH + c, xa);
    }

    for (int p = threadIdx.x; p < NPAIR; p += blockDim.x) {
        int i = 0, rem = p;
        while (rem >= (CH - 1 - i)) { rem -= (CH - 1 - i); i++; }
        int j = i + 1 + rem;

        float acc = 0.0f;
        for (int t = 0; t < len; t++)
            acc += xs[t][i] * xs[t + 1][j] - xs[t][j] * xs[t + 1][i];

        float xai = xs[0][i], xaj = xs[0][j];
        float inci = xs[len][i] - xai;
        float incj = xs[len][j] - xaj;
        st_splitA(base + CH + p, 0.5f * (acc - xai * incj + xaj * inci));
    }
}

// ============================================================
// Pack B: w_ih fp32 -> fp16 (hi only), row-major padded
// ============================================================
__global__ void k_packB(const float* __restrict__ w_ih) {  // grid (34, 16)
    int kc = blockIdx.x, nt = blockIdx.y;
    for (int u = threadIdx.x; u < 1024; u += 128) {
        int r = u >> 3, cu = u & 7;
        int n = nt * 128 + r, k = kc * 64 + cu * 8;
        float v[8] = {0,0,0,0,0,0,0,0};
        if (k < INSZ) {
            const float* src = w_ih + (size_t)n * INSZ + k;
            float4 a = *(const float4*)src, b2 = *(const float4*)(src + 4);
            v[0]=a.x; v[1]=a.y; v[2]=a.z; v[3]=a.w;
            v[4]=b2.x; v[5]=b2.y; v[6]=b2.z; v[7]=b2.w;
        }
        __half h[8];
        #pragma unroll
        for (int i = 0; i < 8; i++) h[i] = __float2half_rn(v[i]);
        *(uint4*)(g_Bh + (size_t)n * KP + k) = *(uint4*)h;
    }
}

// ============================================================
// Kernel 2: HMMA GEMM, fp16 2-term (Ah+Al)*Bh, split-K 2-way.
//   grid (16, 13, 2); z = k-half. 128x128 tile, 256 thr.
// ============================================================
__global__ __launch_bounds__(256, 2)
void k_hmma(const float* __restrict__ b_ih, const float* __restrict__ b_hh) {
    extern __shared__ __align__(128) char smem[];
    uint32_t sb = smem_u32(smem);

    int tid = threadIdx.x;
    int warp = tid >> 5, lane = tid & 31;
    int nbx = blockIdx.x, mby = blockIdx.y;
    int kz0 = blockIdx.z * KHALF;
    int wm = (warp & 3) * 32;
    int wn = (warp >> 2) * 64;

    float acc[2][8][4];
    #pragma unroll
    for (int i = 0; i < 2; i++)
        #pragma unroll
        for (int j = 0; j < 8; j++)
            #pragma unroll
            for (int k = 0; k < 4; k++) acc[i][j][k] = 0.0f;

    auto issue = [&](int stg, int kc) {
        uint32_t dstb = sb + stg * STG_B;
        #pragma unroll
        for (int i = 0; i < 6; i++) {
            const int region = i >> 1;              // 0=Ah 1=Al 2=Bh
            int rem = tid + (i & 1) * 256;          // 0..511
            int r = rem >> 2, q = rem & 3;
            const __half* base =
                (region == 0) ? g_Ah : (region == 1) ? g_Al : g_Bh;
            size_t row = (region < 2) ? (size_t)(mby * 128 + r)
                                      : (size_t)(nbx * 128 + r);
            cpa16(dstb + region * REG_B + r * SROW + q * 16,
                  base + row * KP + kc * 32 + q * 8);
        }
        asm volatile("cp.async.commit_group;");
    };

    issue(0, kz0);

    uint32_t a_row = lane & 15;
    uint32_t a_colq = (lane >> 4) * 8;
    uint32_t b_n = ((lane >> 4) & 1) * 8 + (lane & 7);
    uint32_t b_kq = ((lane >> 3) & 1) * 8;

    for (int kcl = 0; kcl < KHALF; kcl++) {
        int s = kcl & 1;
        asm volatile("cp.async.wait_group 0;" ::: "memory");
        __syncthreads();
        if (kcl + 1 < KHALF) issue(s ^ 1, kz0 + kcl + 1);

        uint32_t stb = sb + s * STG_B;
        #pragma unroll
        for (int k16 = 0; k16 < 32; k16 += 16) {
            uint32_t ah[2][4], al[2][4], bb[8][2];
            #pragma unroll
            for (int mt = 0; mt < 2; mt++) {
                uint32_t ad = stb + (wm + mt * 16 + a_row) * SROW
                            + (a_colq + k16) * 2;
                ldsm4(ah[mt], ad);
                ldsm4(al[mt], ad + REG_B);
            }
            uint32_t bkoff = (k16 + b_kq) * 2;
            #pragma unroll
            for (int np = 0; np < 4; np++) {
                uint32_t bd = stb + 2 * REG_B
                            + (wn + np * 16 + b_n) * SROW + bkoff;
                ldsm4(&bb[np * 2][0], bd);
            }
            #pragma unroll
            for (int mt = 0; mt < 2; mt++)
                #pragma unroll
                for (int nt = 0; nt < 8; nt++) {
                    mma_f16(acc[mt][nt], ah[mt], bb[nt]);
                    mma_f16(acc[mt][nt], al[mt], bb[nt]);
                }
        }
        __syncthreads();
    }

    float* dst = (blockIdx.z == 0) ? g_gx : g_gx2;
    int tr = lane >> 2;
    int tc = (lane & 3) * 2;
    #pragma unroll
    for (int mt = 0; mt < 2; mt++) {
        #pragma unroll
        for (int nt = 0; nt < 8; nt++) {
            int col = nbx * 128 + wn + nt * 8 + tc;
            float bs0 = 0.0f, bs1 = 0.0f;
            if (blockIdx.z == 0) {
                bs0 = b_ih[col] + b_hh[col];
                bs1 = b_ih[col + 1] + b_hh[col + 1];
            }
            int m0 = mby * 128 + wm + mt * 16 + tr;
            float* d = acc[mt][nt];
            if (m0 < MROWS) {
                float2 v = {d[0] + bs0, d[1] + bs1};
                *(float2*)(dst + (size_t)m0 * G4 + col) = v;
            }
            if (m0 + 8 < MROWS) {
                float2 v = {d[2] + bs0, d[3] + bs1};
                *(float2*)(dst + (size_t)(m0 + 8) * G4 + col) = v;
            }
        }
    }
}

// ============================================================
// Kernel 3: PERSISTENT LSTM (pair-packed h; gx = g_gx + g_gx2)
// ============================================================
__global__ __launch_bounds__(LTHR, 1)
void k_lstm_persist(const float* __restrict__ whh,
                    float* __restrict__ out) {
    __shared__ float ws[16 * NH];
    __shared__ float ps[8 * 16 * 32];

    int tid  = threadIdx.x;
    int warp = tid >> 5;
    int lane = tid & 31;
    int n0 = blockIdx.x * 4;
    int kw = warp * 64;

    for (int i = tid; i < 16 * (NH / 4); i += LTHR) {
        int r = i >> 7, kq = i & 127;
        int g = r >> 2, u = r & 3;
        ((float4*)ws)[r * (NH / 4) + kq] =
            ((const float4*)(whh + ((size_t)g * NH + n0 + u) * NH))[kq];
    }
    __syncthreads();

    float cc = 0.0f;
    int ub_u = tid >> 5;
    int ub_b = tid & 31;
    int hidx = ((n0 + ub_u) >> 1) * 64 + ub_b * 2 + ((n0 + ub_u) & 1);

    ull hreg[32];
    #pragma unroll
    for (int i = 0; i < 32; i++) hreg[i] = 0ull;

    float pgx[4];
    if (tid < 128) {
        size_t off = (size_t)ub_b * NSEG * G4;
        #pragma unroll
        for (int g = 0; g < 4; g++) {
            size_t idx = off + g * NH + n0 + ub_u;
            pgx[g] = g_gx[idx] + g_gx2[idx];
        }
    }

    for (int s = 0; s < NSEG; s++) {
        if (s > 0) {
            ull acc2[16];
            #pragma unroll
            for (int r = 0; r < 16; r++) acc2[r] = 0ull;

            #pragma unroll
            for (int kk4 = 0; kk4 < 16; kk4++) {
                ull h0 = hreg[2 * kk4], h1 = hreg[2 * kk4 + 1];
                #pragma unroll
                for (int r = 0; r < 16; r++) {
                    ulonglong2 wv = *(const ulonglong2*)&ws[r * NH + kw + kk4 * 4];
                    fma2(acc2[r], wv.x, h0);
                    fma2(acc2[r], wv.y, h1);
                }
            }
            #pragma unroll
            for (int r = 0; r < 16; r++) {
                float2 v = unpk(acc2[r]);
                ps[(warp * 16 + r) * 32 + lane] = v.x + v.y;
            }
        }
        __syncthreads();

        if (tid < 128) {
            int b = ub_b, u = ub_u;
            float gsum[4];
            #pragma unroll
            for (int g = 0; g < 4; g++) {
                float a = pgx[g];
                if (s > 0) {
                    int row = g * 4 + u;
                    #pragma unroll
                    for (int w = 0; w < 8; w++)
                        a += ps[(w * 16 + row) * 32 + b];
                }
                gsum[g] = a;
            }
            float gi = 1.0f / (1.0f + expf(-gsum[0]));
            float gf = 1.0f / (1.0f + expf(-gsum[1]));
            float gg = tanhf(gsum[2]);
            float go = 1.0f / (1.0f + expf(-gsum[3]));

            float cn = gf * cc + gi * gg;
            float hn = go * tanhf(cn);
            cc = cn;

            g_hP[s & 1][hidx] = hn;
            out[((size_t)b * NSEG + s) * NH + n0 + u] = hn;
        }

        if (s < NSEG - 1) {
            if (tid < 128) {
                size_t off = ((size_t)ub_b * NSEG + s + 1) * G4;
                #pragma unroll
                for (int g = 0; g < 4; g++) {
                    size_t idx = off + g * NH + n0 + ub_u;
                    pgx[g] = g_gx[idx] + g_gx2[idx];
                }
            }

            __syncthreads();
            if (tid == 0) {
                asm volatile("red.release.gpu.global.add.u32 [%0], 1;"
                             :: "l"(&g_bar[s]) : "memory");
                unsigned v;
                do {
                    asm volatile("ld.acquire.gpu.global.u32 %0, [%1];"
                                 : "=r"(v) : "l"(&g_bar[s]) : "memory");
                } while (v < LBLK);
            }
            __syncthreads();

            const float2* src = (const float2*)g_hP[s & 1] + (kw >> 1) * 32 + lane;
            #pragma unroll
            for (int i = 0; i < 32; i++) {
                float2 v = __ldcg(src + i * 32);
                hreg[i] = pack2(v.x, v.y);
            }
        }
    }
}

// ============================================================
extern "C" void kernel_launch(void* const* d_in, const int* in_sizes, int n_in,
                              void* d_out, int out_size) {
    const float* x    = (const float*)d_in[0];
    const float* w_ih = (const float*)d_in[1];
    const float* w_hh = (const float*)d_in[2];
    const float* b_ih = (const float*)d_in[3];
    const float* b_hh = (const float*)d_in[4];
    float* out = (float*)d_out;

    SegArgs seg;
    const double step = 599.0 / 50.0;
    int tv[NSEG + 1];
    for (int i = 0; i <= NSEG; i++)
        tv[i] = (int)nearbyint(1.0 + step * (double)i);
    tv[NSEG] = TLEN;
    for (int s = 0; s < NSEG; s++) {
        seg.start[s] = tv[s] - 1;
        int len = tv[s + 1] - tv[s];
        if (len > 16) len = 16;
        seg.len[s] = len;
    }

    cudaFuncSetAttribute(k_hmma, cudaFuncAttributeMaxDynamicSharedMemorySize, SM_HMMA);

    k_reset<<<1, 64>>>();
    k_feats<<<MROWS, 256>>>(x, seg);
    k_packB<<<dim3(34, 16), 128>>>(w_ih);
    k_hmma<<<dim3(16, 13, 2), 256, SM_HMMA>>>(b_ih, b_hh);
    k_lstm_persist<<<LBLK, LTHR>>>(w_hh, out);
}

// round 11
// speedup vs baseline: 8.0989x; 1.1055x over previous
#include <cuda_runtime.h>
#include <cuda_fp16.h>
#include <cstdint>
#include <math.h>

#define BATCH 32
#define TLEN  600
#define CH    64
#define NSEG  50
#define NH    512
#define NPAIR (CH*(CH-1)/2)      // 2016
#define LOGSIG_CH (CH + NPAIR)   // 2080
#define INSZ  (LOGSIG_CH + CH)   // 2144
#define G4    (4*NH)             // 2048
#define MROWS (BATCH*NSEG)       // 1600

#define LBLK  128
#define LTHR  256

// --- HMMA GEMM geometry ---
#define MP   1664
#define KP   2176
#define KHALF 34
#define SROW 80
#define REG_B 10240
#define STG_B (3 * REG_B)
#define SM_HMMA (2 * STG_B)

typedef unsigned long long ull;

// ---- scratch (no allocations; zero-init, padded regions never written) ----
__device__ float g_gx [MROWS * G4];
__device__ float g_gx2[MROWS * G4];
__device__ float g_hP[2][NH * BATCH];
__device__ unsigned int g_flag[NSEG][8];    // per-(step,chunk) arrival counters
__device__ __half g_Ah[MP * KP];
__device__ __half g_Al[MP * KP];
__device__ __half g_Bh[(size_t)G4 * KP];

struct SegArgs { int start[NSEG]; int len[NSEG]; };

// ================= helpers =================
__device__ __forceinline__ uint32_t smem_u32(const void* p) {
    uint32_t a;
    asm("{ .reg .u64 t; cvta.to.shared.u64 t, %1; cvt.u32.u64 %0, t; }"
        : "=r"(a) : "l"(p));
    return a;
}
__device__ __forceinline__ void ldsm4(uint32_t* r, uint32_t addr) {
    asm volatile("ldmatrix.sync.aligned.m8n8.x4.shared.b16 {%0,%1,%2,%3}, [%4];"
        : "=r"(r[0]), "=r"(r[1]), "=r"(r[2]), "=r"(r[3]) : "r"(addr));
}
__device__ __forceinline__ void mma_f16(float* d, const uint32_t* a, const uint32_t* b) {
    asm volatile(
        "mma.sync.aligned.m16n8k16.row.col.f32.f16.f16.f32 "
        "{%0,%1,%2,%3}, {%4,%5,%6,%7}, {%8,%9}, {%0,%1,%2,%3};"
        : "+f"(d[0]), "+f"(d[1]), "+f"(d[2]), "+f"(d[3])
        : "r"(a[0]), "r"(a[1]), "r"(a[2]), "r"(a[3]), "r"(b[0]), "r"(b[1]));
}
__device__ __forceinline__ void cpa16(uint32_t dst, const void* src) {
    asm volatile("cp.async.cg.shared.global [%0], [%1], 16;" :: "r"(dst), "l"(src));
}
__device__ __forceinline__ void fma2(ull& d, ull a, ull b) {
    asm("fma.rn.f32x2 %0, %1, %2, %0;" : "+l"(d) : "l"(a), "l"(b));
}
__device__ __forceinline__ float2 unpk(ull v) {
    float2 r;
    asm("mov.b64 {%0, %1}, %2;" : "=f"(r.x), "=f"(r.y) : "l"(v));
    return r;
}
__device__ __forceinline__ ull pack2(float x, float y) {
    ull r;
    asm("mov.b64 %0, {%1, %2};" : "=l"(r) : "f"(x), "f"(y));
    return r;
}
__device__ __forceinline__ void st_splitA(size_t idx, float v) {
    __half h = __float2half_rn(v);
    g_Ah[idx] = h;
    g_Al[idx] = __float2half_rn(v - __half2float(h));
}

// ============================================================
__global__ void k_reset() {
    int i = threadIdx.x;
    if (i < NSEG * 8) ((unsigned int*)g_flag)[i] = 0u;
}

// ============================================================
// Kernel 1: log-signature features -> split fp16 A operand
// ============================================================
__global__ void k_feats(const float* __restrict__ x, SegArgs seg) {
    int bs = blockIdx.x;
    int b = bs / NSEG, s = bs % NSEG;
    int st = seg.start[s], len = seg.len[s];

    __shared__ float xs[17][CH];
    const float* xp = x + ((size_t)b * TLEN + st) * CH;
    for (int idx = threadIdx.x; idx < (len + 1) * CH; idx += blockDim.x)
        xs[idx >> 6][idx & 63] = xp[idx];
    __syncthreads();

    size_t base = (size_t)bs * KP;

    if (threadIdx.x < CH) {
        int c = threadIdx.x;
        float xa = xs[0][c], xe = xs[len][c];
        st_splitA(base + c, xe - xa);
        st_splitA(base + LOGSIG_CH + c, xa);
    }

    for (int p = threadIdx.x; p < NPAIR; p += blockDim.x) {
        int i = 0, rem = p;
        while (rem >= (CH - 1 - i)) { rem -= (CH - 1 - i); i++; }
        int j = i + 1 + rem;

        float acc = 0.0f;
        for (int t = 0; t < len; t++)
            acc += xs[t][i] * xs[t + 1][j] - xs[t][j] * xs[t + 1][i];

        float xai = xs[0][i], xaj = xs[0][j];
        float inci = xs[len][i] - xai;
        float incj = xs[len][j] - xaj;
        st_splitA(base + CH + p, 0.5f * (acc - xai * incj + xaj * inci));
    }
}

// ============================================================
// Pack B: w_ih fp32 -> fp16 (hi only), row-major padded
// ============================================================
__global__ void k_packB(const float* __restrict__ w_ih) {  // grid (34, 16)
    int kc = blockIdx.x, nt = blockIdx.y;
    for (int u = threadIdx.x; u < 1024; u += 128) {
        int r = u >> 3, cu = u & 7;
        int n = nt * 128 + r, k = kc * 64 + cu * 8;
        float v[8] = {0,0,0,0,0,0,0,0};
        if (k < INSZ) {
            const float* src = w_ih + (size_t)n * INSZ + k;
            float4 a = *(const float4*)src, b2 = *(const float4*)(src + 4);
            v[0]=a.x; v[1]=a.y; v[2]=a.z; v[3]=a.w;
            v[4]=b2.x; v[5]=b2.y; v[6]=b2.z; v[7]=b2.w;
        }
        __half h[8];
        #pragma unroll
        for (int i = 0; i < 8; i++) h[i] = __float2half_rn(v[i]);
        *(uint4*)(g_Bh + (size_t)n * KP + k) = *(uint4*)h;
    }
}

// ============================================================
// Kernel 2: HMMA GEMM, fp16 2-term (Ah+Al)*Bh, split-K 2-way.
// ============================================================
__global__ __launch_bounds__(256, 2)
void k_hmma(const float* __restrict__ b_ih, const float* __restrict__ b_hh) {
    extern __shared__ __align__(128) char smem[];
    uint32_t sb = smem_u32(smem);

    int tid = threadIdx.x;
    int warp = tid >> 5, lane = tid & 31;
    int nbx = blockIdx.x, mby = blockIdx.y;
    int kz0 = blockIdx.z * KHALF;
    int wm = (warp & 3) * 32;
    int wn = (warp >> 2) * 64;

    float acc[2][8][4];
    #pragma unroll
    for (int i = 0; i < 2; i++)
        #pragma unroll
        for (int j = 0; j < 8; j++)
            #pragma unroll
            for (int k = 0; k < 4; k++) acc[i][j][k] = 0.0f;

    auto issue = [&](int stg, int kc) {
        uint32_t dstb = sb + stg * STG_B;
        #pragma unroll
        for (int i = 0; i < 6; i++) {
            const int region = i >> 1;
            int rem = tid + (i & 1) * 256;
            int r = rem >> 2, q = rem & 3;
            const __half* base =
                (region == 0) ? g_Ah : (region == 1) ? g_Al : g_Bh;
            size_t row = (region < 2) ? (size_t)(mby * 128 + r)
                                      : (size_t)(nbx * 128 + r);
            cpa16(dstb + region * REG_B + r * SROW + q * 16,
                  base + row * KP + kc * 32 + q * 8);
        }
        asm volatile("cp.async.commit_group;");
    };

    issue(0, kz0);

    uint32_t a_row = lane & 15;
    uint32_t a_colq = (lane >> 4) * 8;
    uint32_t b_n = ((lane >> 4) & 1) * 8 + (lane & 7);
    uint32_t b_kq = ((lane >> 3) & 1) * 8;

    for (int kcl = 0; kcl < KHALF; kcl++) {
        int s = kcl & 1;
        asm volatile("cp.async.wait_group 0;" ::: "memory");
        __syncthreads();
        if (kcl + 1 < KHALF) issue(s ^ 1, kz0 + kcl + 1);

        uint32_t stb = sb + s * STG_B;
        #pragma unroll
        for (int k16 = 0; k16 < 32; k16 += 16) {
            uint32_t ah[2][4], al[2][4], bb[8][2];
            #pragma unroll
            for (int mt = 0; mt < 2; mt++) {
                uint32_t ad = stb + (wm + mt * 16 + a_row) * SROW
                            + (a_colq + k16) * 2;
                ldsm4(ah[mt], ad);
                ldsm4(al[mt], ad + REG_B);
            }
            uint32_t bkoff = (k16 + b_kq) * 2;
            #pragma unroll
            for (int np = 0; np < 4; np++) {
                uint32_t bd = stb + 2 * REG_B
                            + (wn + np * 16 + b_n) * SROW + bkoff;
                ldsm4(&bb[np * 2][0], bd);
            }
            #pragma unroll
            for (int mt = 0; mt < 2; mt++)
                #pragma unroll
                for (int nt = 0; nt < 8; nt++) {
                    mma_f16(acc[mt][nt], ah[mt], bb[nt]);
                    mma_f16(acc[mt][nt], al[mt], bb[nt]);
                }
        }
        __syncthreads();
    }

    float* dst = (blockIdx.z == 0) ? g_gx : g_gx2;
    int tr = lane >> 2;
    int tc = (lane & 3) * 2;
    #pragma unroll
    for (int mt = 0; mt < 2; mt++) {
        #pragma unroll
        for (int nt = 0; nt < 8; nt++) {
            int col = nbx * 128 + wn + nt * 8 + tc;
            float bs0 = 0.0f, bs1 = 0.0f;
            if (blockIdx.z == 0) {
                bs0 = b_ih[col] + b_hh[col];
                bs1 = b_ih[col + 1] + b_hh[col + 1];
            }
            int m0 = mby * 128 + wm + mt * 16 + tr;
            float* d = acc[mt][nt];
            if (m0 < MROWS) {
                float2 v = {d[0] + bs0, d[1] + bs1};
                *(float2*)(dst + (size_t)m0 * G4 + col) = v;
            }
            if (m0 + 8 < MROWS) {
                float2 v = {d[2] + bs0, d[3] + bs1};
                *(float2*)(dst + (size_t)(m0 + 8) * G4 + col) = v;
            }
        }
    }
}

// ============================================================
// Kernel 3: PERSISTENT LSTM with fine-grained per-chunk flags.
//   Warp w needs h[w*64 .. w*64+64), produced by blocks
//   16*w .. 16*w+15. Each warp polls ONLY its chunk counter
//   and starts its matvec as soon as its window is ready.
//   No full grid barrier. Skew bounded <2 steps by the flag
//   dependency chain, so parity double-buffering is safe.
// ============================================================
__global__ __launch_bounds__(LTHR, 1)
void k_lstm_persist(const float* __restrict__ whh,
                    float* __restrict__ out) {
    __shared__ float ws[16 * NH];
    __shared__ float ps[8 * 16 * 32];

    int tid  = threadIdx.x;
    int warp = tid >> 5;
    int lane = tid & 31;
    int n0 = blockIdx.x * 4;
    int kw = warp * 64;
    int mychunk = blockIdx.x >> 4;     // chunk this block's h feeds

    for (int i = tid; i < 16 * (NH / 4); i += LTHR) {
        int r = i >> 7, kq = i & 127;
        int g = r >> 2, u = r & 3;
        ((float4*)ws)[r * (NH / 4) + kq] =
            ((const float4*)(whh + ((size_t)g * NH + n0 + u) * NH))[kq];
    }
    __syncthreads();

    float cc = 0.0f;
    int ub_u = tid >> 5;
    int ub_b = tid & 31;
    int hidx = ((n0 + ub_u) >> 1) * 64 + ub_b * 2 + ((n0 + ub_u) & 1);

    float pgx[4];
    if (tid < 128) {
        size_t off = (size_t)ub_b * NSEG * G4;
        #pragma unroll
        for (int g = 0; g < 4; g++) {
            size_t idx = off + g * NH + n0 + ub_u;
            pgx[g] = g_gx[idx] + g_gx2[idx];
        }
    }

    for (int s = 0; s < NSEG; s++) {
        if (s > 0) {
            // ---- wait for THIS warp's h window (chunk = warp id) ----
            const unsigned int* fp = &g_flag[s - 1][warp];
            unsigned int v;
            do {
                asm volatile("ld.acquire.gpu.global.u32 %0, [%1];"
                             : "=r"(v) : "l"(fp) : "memory");
            } while (v < 16u);

            // ---- load h window (coalesced, L2) ----
            ull hreg[32];
            const float2* src = (const float2*)g_hP[(s - 1) & 1]
                              + (kw >> 1) * 32 + lane;
            #pragma unroll
            for (int i = 0; i < 32; i++) {
                float2 hv = __ldcg(src + i * 32);
                hreg[i] = pack2(hv.x, hv.y);
            }

            // ---- matvec partials over this warp's k-window ----
            ull acc2[16];
            #pragma unroll
            for (int r = 0; r < 16; r++) acc2[r] = 0ull;

            #pragma unroll
            for (int kk4 = 0; kk4 < 16; kk4++) {
                ull h0 = hreg[2 * kk4], h1 = hreg[2 * kk4 + 1];
                #pragma unroll
                for (int r = 0; r < 16; r++) {
                    ulonglong2 wv = *(const ulonglong2*)&ws[r * NH + kw + kk4 * 4];
                    fma2(acc2[r], wv.x, h0);
                    fma2(acc2[r], wv.y, h1);
                }
            }
            #pragma unroll
            for (int r = 0; r < 16; r++) {
                float2 v2 = unpk(acc2[r]);
                ps[(warp * 16 + r) * 32 + lane] = v2.x + v2.y;
            }
        }
        __syncthreads();

        // ---- cell update (threads 0..127): thread (u,b) ----
        if (tid < 128) {
            int b = ub_b, u = ub_u;
            float gsum[4];
            #pragma unroll
            for (int g = 0; g < 4; g++) {
                float a = pgx[g];
                if (s > 0) {
                    int row = g * 4 + u;
                    #pragma unroll
                    for (int w = 0; w < 8; w++)
                        a += ps[(w * 16 + row) * 32 + b];
                }
                gsum[g] = a;
            }
            float gi = 1.0f / (1.0f + expf(-gsum[0]));
            float gf = 1.0f / (1.0f + expf(-gsum[1]));
            float gg = tanhf(gsum[2]);
            float go = 1.0f / (1.0f + expf(-gsum[3]));

            float cn = gf * cc + gi * gg;
            float hn = go * tanhf(cn);
            cc = cn;

            g_hP[s & 1][hidx] = hn;
            out[((size_t)b * NSEG + s) * NH + n0 + u] = hn;
        }
        __syncthreads();   // h stores done block-wide; also protects ps reuse

        if (s < NSEG - 1) {
            // ---- publish this block's chunk contribution for step s ----
            if (tid == 0) {
                asm volatile("red.release.gpu.global.add.u32 [%0], 1;"
                             :: "l"(&g_flag[s][mychunk]) : "memory");
            }
            // ---- prefetch gx(s+1): hidden under next flag-wait/matvec ----
            if (tid < 128) {
                size_t off = ((size_t)ub_b * NSEG + s + 1) * G4;
                #pragma unroll
                for (int g = 0; g < 4; g++) {
                    size_t idx = off + g * NH + n0 + ub_u;
                    pgx[g] = g_gx[idx] + g_gx2[idx];
                }
            }
        }
    }
}

// ============================================================
extern "C" void kernel_launch(void* const* d_in, const int* in_sizes, int n_in,
                              void* d_out, int out_size) {
    const float* x    = (const float*)d_in[0];
    const float* w_ih = (const float*)d_in[1];
    const float* w_hh = (const float*)d_in[2];
    const float* b_ih = (const float*)d_in[3];
    const float* b_hh = (const float*)d_in[4];
    float* out = (float*)d_out;

    SegArgs seg;
    const double step = 599.0 / 50.0;
    int tv[NSEG + 1];
    for (int i = 0; i <= NSEG; i++)
        tv[i] = (int)nearbyint(1.0 + step * (double)i);
    tv[NSEG] = TLEN;
    for (int s = 0; s < NSEG; s++) {
        seg.start[s] = tv[s] - 1;
        int len = tv[s + 1] - tv[s];
        if (len > 16) len = 16;
        seg.len[s] = len;
    }

    cudaFuncSetAttribute(k_hmma, cudaFuncAttributeMaxDynamicSharedMemorySize, SM_HMMA);

    k_reset<<<1, 512>>>();
    k_feats<<<MROWS, 256>>>(x, seg);
    k_packB<<<dim3(34, 16), 128>>>(w_ih);
    k_hmma<<<dim3(16, 13, 2), 256, SM_HMMA>>>(b_ih, b_hh);
    k_lstm_persist<<<LBLK, LTHR>>>(w_hh, out);
}